// round 1
// baseline (speedup 1.0000x reference)
#include <cuda_runtime.h>
#include <math.h>

#define HH 256
#define WW 256
#define CCH 256
#define NROI 1024
#define ICN 12544          // 256 * 49
#define FC 1024
#define NOUT 49

// ---------------- scratch (device globals; no allocations allowed) ----------
__device__ float g_feat_t[(size_t)2 * 256 * 256 * 256];  // (B,H,W,C) 134MB
__device__ float g_x[(size_t)NROI * ICN];                // (n,C,7,7)  51MB
__device__ float g_hid[(size_t)NROI * FC];               // 4MB
__device__ float g_mask[NROI * NOUT];

// ---------------- kernel 1: transpose (B,C,H,W) -> (B,H,W,C) -----------------
__global__ void transpose_kernel(const float* __restrict__ f) {
    __shared__ float tile[32][33];
    int b = blockIdx.z;
    int hw0 = blockIdx.x * 32;
    int c0 = blockIdx.y * 32;
    int tx = threadIdx.x, ty = threadIdx.y;
    const float* src = f + ((size_t)b * CCH) * (HH * WW);
#pragma unroll
    for (int i = 0; i < 32; i += 8)
        tile[ty + i][tx] = src[(size_t)(c0 + ty + i) * (HH * WW) + hw0 + tx];
    __syncthreads();
    float* dst = g_feat_t + ((size_t)b << 24);
#pragma unroll
    for (int i = 0; i < 32; i += 8)
        dst[(size_t)(hw0 + ty + i) * CCH + c0 + tx] = tile[tx][ty + i];
}

// ---------------- kernel 2: rotated roi-align --------------------------------
struct alignas(16) Samp { int yl, xl, yh, xh; float w11, w12, w21, w22; };

__global__ void __launch_bounds__(256) roi_kernel(const float* __restrict__ rois) {
    __shared__ Samp samp[196];
    __shared__ float tile[25][257];
    int n = blockIdx.x;
    int tid = threadIdx.x;

    const float* r = rois + n * 6;
    int b = (int)r[0];
    float cx = r[1] * 0.125f;
    float cy = r[2] * 0.125f;
    float rw = fmaxf(r[3] * 0.125f, 1.0f);
    float rh = fmaxf(r[4] * 0.125f, 1.0f);
    float theta = r[5];
    float st, ct;
    sincosf(theta, &st, &ct);
    float bw = rw / 7.0f;
    float bh = rh / 7.0f;

    if (tid < 196) {
        int bin = tid >> 2;
        int s = tid & 3;
        int ph = bin / 7, pw = bin - ph * 7;
        int sy = s >> 1, sx = s & 1;
        float yy = -rh * 0.5f + ((float)ph + 0.25f + 0.5f * (float)sy) * bh;
        float xx = -rw * 0.5f + ((float)pw + 0.25f + 0.5f * (float)sx) * bw;
        float xs = xx * ct - yy * st + cx;
        float ys = xx * st + yy * ct + cy;
        bool valid = (ys > -1.0f) && (ys < (float)HH) && (xs > -1.0f) && (xs < (float)WW);
        float ysc = fminf(fmaxf(ys, 0.0f), (float)(HH - 1));
        float xsc = fminf(fmaxf(xs, 0.0f), (float)(WW - 1));
        int yl = (int)floorf(ysc);
        int xl = (int)floorf(xsc);
        int yh = min(yl + 1, HH - 1);
        int xh = min(xl + 1, WW - 1);
        float ly = ysc - (float)yl;
        float lx = xsc - (float)xl;
        float hy = 1.0f - ly, hx = 1.0f - lx;
        float vf = valid ? 0.25f : 0.0f;   // fold mean(4 samples) + valid mask
        Samp sp;
        sp.yl = yl; sp.xl = xl; sp.yh = yh; sp.xh = xh;
        sp.w11 = hy * hx * vf; sp.w12 = hy * lx * vf;
        sp.w21 = ly * hx * vf; sp.w22 = ly * lx * vf;
        samp[tid] = sp;
    }
    __syncthreads();

    // thread tid = channel c; corner reads are coalesced 1KB vectors.
    const float* ft = g_feat_t + ((size_t)b << 24) + tid;
    float* xo = g_x + (size_t)n * ICN;

    // ---- chunk 0: bins 0..24 ----
#pragma unroll 1
    for (int bl = 0; bl < 25; bl++) {
        float acc = 0.0f;
#pragma unroll
        for (int s = 0; s < 4; s++) {
            const Samp* sp = &samp[bl * 4 + s];
            int4 id = *(const int4*)(&sp->yl);
            float4 w = *(const float4*)(&sp->w11);
            int rl = id.x << 16, ch = id.w << 8;
            int rh2 = id.z << 16, cl = id.y << 8;
            float v11 = ft[rl + cl];
            float v12 = ft[rl + ch];
            float v21 = ft[rh2 + cl];
            float v22 = ft[rh2 + ch];
            acc += w.x * v11 + w.y * v12 + w.z * v21 + w.w * v22;
        }
        tile[bl][tid] = acc;
    }
    __syncthreads();
    for (int i = tid; i < 256 * 25; i += 256) {
        int c = i / 25;
        int hwl = i - c * 25;
        xo[c * 49 + hwl] = tile[hwl][c];
    }
    __syncthreads();

    // ---- chunk 1: bins 25..48 ----
#pragma unroll 1
    for (int bl = 0; bl < 24; bl++) {
        int bin = 25 + bl;
        float acc = 0.0f;
#pragma unroll
        for (int s = 0; s < 4; s++) {
            const Samp* sp = &samp[bin * 4 + s];
            int4 id = *(const int4*)(&sp->yl);
            float4 w = *(const float4*)(&sp->w11);
            int rl = id.x << 16, ch = id.w << 8;
            int rh2 = id.z << 16, cl = id.y << 8;
            float v11 = ft[rl + cl];
            float v12 = ft[rl + ch];
            float v21 = ft[rh2 + cl];
            float v22 = ft[rh2 + ch];
            acc += w.x * v11 + w.y * v12 + w.z * v21 + w.w * v22;
        }
        tile[bl][tid] = acc;
    }
    __syncthreads();
    for (int i = tid; i < 256 * 24; i += 256) {
        int c = i / 24;
        int hwl = i - c * 24;
        xo[c * 49 + 25 + hwl] = tile[hwl][c];
    }
}

// ---------------- kernel 3: GEMM1  hid = relu(x @ w1 + b1) -------------------
// M=1024 (rois), N=1024 (fc), K=12544. BM=128, BN=64, BK=16, 128 threads, 8x8.
#define BM 128
#define BN 64
#define BKK 16

__global__ void __launch_bounds__(128) gemm1_kernel(const float* __restrict__ w1,
                                                    const float* __restrict__ b1) {
    __shared__ float As[BKK][BM + 4];   // padded: store A transposed
    __shared__ float Bs[BKK][BN];

    int t = threadIdx.x;
    int n0 = blockIdx.x * BN;
    int m0 = blockIdx.y * BM;

    int ar = t >> 2, ac = t & 3;     // A ldg mapping: 32 rows x 4 float4-cols
    int br = t >> 4, bc = t & 15;    // B ldg mapping: 8 rows x 16 float4-cols
    int tm = t >> 3, tn = t & 7;     // 16 x 8 thread grid, 8x8 microtile

    const float* Abase = g_x + (size_t)m0 * ICN;

    float4 aReg[4], bReg[2];
#pragma unroll
    for (int j = 0; j < 4; j++)
        aReg[j] = *(const float4*)(Abase + (size_t)(ar + 32 * j) * ICN + ac * 4);
#pragma unroll
    for (int j = 0; j < 2; j++)
        bReg[j] = *(const float4*)(w1 + (size_t)(br + 8 * j) * FC + n0 + bc * 4);

    float acc[8][8];
#pragma unroll
    for (int i = 0; i < 8; i++)
#pragma unroll
        for (int j = 0; j < 8; j++) acc[i][j] = 0.0f;

    const int KT = ICN / BKK;   // 784
    for (int kt = 0; kt < KT; kt++) {
#pragma unroll
        for (int j = 0; j < 4; j++) {
            As[ac * 4 + 0][ar + 32 * j] = aReg[j].x;
            As[ac * 4 + 1][ar + 32 * j] = aReg[j].y;
            As[ac * 4 + 2][ar + 32 * j] = aReg[j].z;
            As[ac * 4 + 3][ar + 32 * j] = aReg[j].w;
        }
#pragma unroll
        for (int j = 0; j < 2; j++)
            *(float4*)(&Bs[br + 8 * j][bc * 4]) = bReg[j];
        __syncthreads();

        if (kt + 1 < KT) {
            int k0 = (kt + 1) * BKK;
#pragma unroll
            for (int j = 0; j < 4; j++)
                aReg[j] = *(const float4*)(Abase + (size_t)(ar + 32 * j) * ICN + k0 + ac * 4);
#pragma unroll
            for (int j = 0; j < 2; j++)
                bReg[j] = *(const float4*)(w1 + (size_t)(k0 + br + 8 * j) * FC + n0 + bc * 4);
        }

#pragma unroll
        for (int k = 0; k < BKK; k++) {
            float4 a0 = *(const float4*)(&As[k][tm * 8]);
            float4 a1 = *(const float4*)(&As[k][tm * 8 + 4]);
            float4 b0 = *(const float4*)(&Bs[k][tn * 8]);
            float4 b1v = *(const float4*)(&Bs[k][tn * 8 + 4]);
            float av[8] = {a0.x, a0.y, a0.z, a0.w, a1.x, a1.y, a1.z, a1.w};
            float bv[8] = {b0.x, b0.y, b0.z, b0.w, b1v.x, b1v.y, b1v.z, b1v.w};
#pragma unroll
            for (int i = 0; i < 8; i++)
#pragma unroll
                for (int j = 0; j < 8; j++)
                    acc[i][j] += av[i] * bv[j];
        }
        __syncthreads();
    }

    // epilogue: + bias, relu
    float bb[8];
#pragma unroll
    for (int j = 0; j < 8; j++) bb[j] = b1[n0 + tn * 8 + j];
#pragma unroll
    for (int i = 0; i < 8; i++) {
        int row = m0 + tm * 8 + i;
        float* o = g_hid + (size_t)row * FC + n0 + tn * 8;
        float4 v0, v1;
        v0.x = fmaxf(acc[i][0] + bb[0], 0.0f);
        v0.y = fmaxf(acc[i][1] + bb[1], 0.0f);
        v0.z = fmaxf(acc[i][2] + bb[2], 0.0f);
        v0.w = fmaxf(acc[i][3] + bb[3], 0.0f);
        v1.x = fmaxf(acc[i][4] + bb[4], 0.0f);
        v1.y = fmaxf(acc[i][5] + bb[5], 0.0f);
        v1.z = fmaxf(acc[i][6] + bb[6], 0.0f);
        v1.w = fmaxf(acc[i][7] + bb[7], 0.0f);
        *(float4*)(o) = v0;
        *(float4*)(o + 4) = v1;
    }
}

// ---------------- kernel 4: GEMM2 + sigmoid ----------------------------------
__global__ void __launch_bounds__(64) gemm2_kernel(const float* __restrict__ w2,
                                                   const float* __restrict__ b2) {
    __shared__ float sh[FC];
    int n = blockIdx.x;
    int tid = threadIdx.x;
    for (int k = tid; k < FC; k += 64) sh[k] = g_hid[(size_t)n * FC + k];
    __syncthreads();
    if (tid < NOUT) {
        float acc = b2[tid];
#pragma unroll 8
        for (int k = 0; k < FC; k++)
            acc += sh[k] * w2[k * NOUT + tid];
        g_mask[n * NOUT + tid] = 1.0f / (1.0f + expf(-acc));
    }
}

// ---------------- kernel 5: out = x * mask -----------------------------------
__global__ void modulate_kernel(float* __restrict__ out, int total) {
    int idx = blockIdx.x * blockDim.x + threadIdx.x;
    if (idx >= total) return;
    int n = idx / ICN;
    int rem = idx - n * ICN;
    int hw = rem % NOUT;
    out[idx] = g_x[idx] * g_mask[n * NOUT + hw];
}

// ---------------- launcher ---------------------------------------------------
extern "C" void kernel_launch(void* const* d_in, const int* in_sizes, int n_in,
                              void* d_out, int out_size) {
    const float* features = (const float*)d_in[0];
    const float* rois     = (const float*)d_in[1];
    const float* w1       = (const float*)d_in[2];
    const float* b1       = (const float*)d_in[3];
    const float* w2       = (const float*)d_in[4];
    const float* b2       = (const float*)d_in[5];
    float* out = (float*)d_out;

    transpose_kernel<<<dim3((HH * WW) / 32, CCH / 32, 2), dim3(32, 8)>>>(features);
    roi_kernel<<<NROI, 256>>>(rois);
    gemm1_kernel<<<dim3(FC / BN, NROI / BM), 128>>>(w1, b1);
    gemm2_kernel<<<NROI, 64>>>(w2, b2);
    int total = NROI * ICN;
    modulate_kernel<<<(total + 255) / 256, 256>>>(out, total);
}

// round 2
// speedup vs baseline: 1.1591x; 1.1591x over previous
#include <cuda_runtime.h>
#include <math.h>
#include <stdint.h>

#define HH 256
#define WW 256
#define CCH 256
#define NROI 1024
#define ICN 12544          // 256 * 49
#define FC 1024
#define NOUT 49

// ---------------- scratch (device globals; no allocations allowed) ----------
__device__ float g_feat_t[(size_t)2 * 256 * 256 * 256];  // (B,H,W,C) 134MB
__device__ float g_x[(size_t)NROI * ICN];                // (n,C,7,7)  51MB
__device__ float g_hid[(size_t)NROI * FC];               // 4MB
__device__ float g_mask[NROI * NOUT];

// ---------------- kernel 1: transpose (B,C,H,W) -> (B,H,W,C) -----------------
__global__ void transpose_kernel(const float* __restrict__ f) {
    __shared__ float tile[32][33];
    int b = blockIdx.z;
    int hw0 = blockIdx.x * 32;
    int c0 = blockIdx.y * 32;
    int tx = threadIdx.x, ty = threadIdx.y;
    const float* src = f + ((size_t)b * CCH) * (HH * WW);
#pragma unroll
    for (int i = 0; i < 32; i += 8)
        tile[ty + i][tx] = src[(size_t)(c0 + ty + i) * (HH * WW) + hw0 + tx];
    __syncthreads();
    float* dst = g_feat_t + ((size_t)b << 24);
#pragma unroll
    for (int i = 0; i < 32; i += 8)
        dst[(size_t)(hw0 + ty + i) * CCH + c0 + tx] = tile[tx][ty + i];
}

// ---------------- kernel 2: rotated roi-align --------------------------------
struct alignas(16) Samp { int yl, xl, yh, xh; float w11, w12, w21, w22; };

__global__ void __launch_bounds__(256) roi_kernel(const float* __restrict__ rois) {
    __shared__ Samp samp[196];
    __shared__ float tile[25][257];
    int n = blockIdx.x;
    int tid = threadIdx.x;

    const float* r = rois + n * 6;
    int b = (int)r[0];
    float cx = r[1] * 0.125f;
    float cy = r[2] * 0.125f;
    float rw = fmaxf(r[3] * 0.125f, 1.0f);
    float rh = fmaxf(r[4] * 0.125f, 1.0f);
    float theta = r[5];
    float st, ct;
    sincosf(theta, &st, &ct);
    float bw = rw / 7.0f;
    float bh = rh / 7.0f;

    if (tid < 196) {
        int bin = tid >> 2;
        int s = tid & 3;
        int ph = bin / 7, pw = bin - ph * 7;
        int sy = s >> 1, sx = s & 1;
        float yy = -rh * 0.5f + ((float)ph + 0.25f + 0.5f * (float)sy) * bh;
        float xx = -rw * 0.5f + ((float)pw + 0.25f + 0.5f * (float)sx) * bw;
        float xs = xx * ct - yy * st + cx;
        float ys = xx * st + yy * ct + cy;
        bool valid = (ys > -1.0f) && (ys < (float)HH) && (xs > -1.0f) && (xs < (float)WW);
        float ysc = fminf(fmaxf(ys, 0.0f), (float)(HH - 1));
        float xsc = fminf(fmaxf(xs, 0.0f), (float)(WW - 1));
        int yl = (int)floorf(ysc);
        int xl = (int)floorf(xsc);
        int yh = min(yl + 1, HH - 1);
        int xh = min(xl + 1, WW - 1);
        float ly = ysc - (float)yl;
        float lx = xsc - (float)xl;
        float hy = 1.0f - ly, hx = 1.0f - lx;
        float vf = valid ? 0.25f : 0.0f;   // fold mean(4 samples) + valid mask
        Samp sp;
        sp.yl = yl; sp.xl = xl; sp.yh = yh; sp.xh = xh;
        sp.w11 = hy * hx * vf; sp.w12 = hy * lx * vf;
        sp.w21 = ly * hx * vf; sp.w22 = ly * lx * vf;
        samp[tid] = sp;
    }
    __syncthreads();

    const float* ft = g_feat_t + ((size_t)b << 24) + tid;
    float* xo = g_x + (size_t)n * ICN;

#pragma unroll 1
    for (int bl = 0; bl < 25; bl++) {
        float acc = 0.0f;
#pragma unroll
        for (int s = 0; s < 4; s++) {
            const Samp* sp = &samp[bl * 4 + s];
            int4 id = *(const int4*)(&sp->yl);
            float4 w = *(const float4*)(&sp->w11);
            int rl = id.x << 16, ch = id.w << 8;
            int rh2 = id.z << 16, cl = id.y << 8;
            float v11 = ft[rl + cl];
            float v12 = ft[rl + ch];
            float v21 = ft[rh2 + cl];
            float v22 = ft[rh2 + ch];
            acc += w.x * v11 + w.y * v12 + w.z * v21 + w.w * v22;
        }
        tile[bl][tid] = acc;
    }
    __syncthreads();
    for (int i = tid; i < 256 * 25; i += 256) {
        int c = i / 25;
        int hwl = i - c * 25;
        xo[c * 49 + hwl] = tile[hwl][c];
    }
    __syncthreads();

#pragma unroll 1
    for (int bl = 0; bl < 24; bl++) {
        int bin = 25 + bl;
        float acc = 0.0f;
#pragma unroll
        for (int s = 0; s < 4; s++) {
            const Samp* sp = &samp[bin * 4 + s];
            int4 id = *(const int4*)(&sp->yl);
            float4 w = *(const float4*)(&sp->w11);
            int rl = id.x << 16, ch = id.w << 8;
            int rh2 = id.z << 16, cl = id.y << 8;
            float v11 = ft[rl + cl];
            float v12 = ft[rl + ch];
            float v21 = ft[rh2 + cl];
            float v22 = ft[rh2 + ch];
            acc += w.x * v11 + w.y * v12 + w.z * v21 + w.w * v22;
        }
        tile[bl][tid] = acc;
    }
    __syncthreads();
    for (int i = tid; i < 256 * 24; i += 256) {
        int c = i / 24;
        int hwl = i - c * 24;
        xo[c * 49 + 25 + hwl] = tile[hwl][c];
    }
}

// ---------------- kernel 3: GEMM1 hid = relu(x @ w1 + b1), tf32 HMMA ---------
// M=1024, N=1024, K=12544. BM=128, BN=64, BK=16, 256 threads (8 warps, 4x2).
// Warp tile 32x32 = MI(2) x NI(4) m16n8k8 fragments.
#define BM 128
#define BN 64
#define BKK 16

__device__ __forceinline__ uint32_t f2tf32(float x) {
    uint32_t u;
    asm("cvt.rna.tf32.f32 %0, %1;" : "=r"(u) : "f"(x));
    return u;
}

__global__ void __launch_bounds__(256) gemm1_kernel(const float* __restrict__ w1,
                                                    const float* __restrict__ b1) {
    // padded so fragment LDS is bank-conflict-free:
    // As row stride 136 (mod32=8), Bs row stride 72 (mod32=8)
    __shared__ uint32_t As[BKK][BM + 8];
    __shared__ uint32_t Bs[BKK][BN + 8];

    int t = threadIdx.x;
    int lane = t & 31;
    int warp = t >> 5;
    int wm = warp >> 1;      // 0..3  (32-row slabs)
    int wn = warp & 1;       // 0..1  (32-col slabs)
    int tig = lane & 3;      // thread-in-group (k/col dim)
    int gid = lane >> 2;     // group id (row dim)

    int n0 = blockIdx.x * BN;
    int m0 = blockIdx.y * BM;

    // global-load mappings
    int ar = t >> 1;                // 0..127  (A row)
    int ac = (t & 1) * 8;           // 0 or 8  (A col base, 8 floats each)
    int br = t >> 4;                // 0..15   (B row)
    int bc = (t & 15) * 4;          // 0..60   (B col base, 4 floats)

    const float* Abase = g_x + (size_t)(m0 + ar) * ICN + ac;
    const float* Bbase = w1 + (size_t)br * FC + n0 + bc;

    float4 aReg0 = *(const float4*)(Abase);
    float4 aReg1 = *(const float4*)(Abase + 4);
    float4 bReg  = *(const float4*)(Bbase);

    float acc[2][4][4];
#pragma unroll
    for (int mi = 0; mi < 2; mi++)
#pragma unroll
        for (int ni = 0; ni < 4; ni++)
#pragma unroll
            for (int j = 0; j < 4; j++) acc[mi][ni][j] = 0.0f;

    const int KT = ICN / BKK;   // 784
    for (int kt = 0; kt < KT; kt++) {
        // stage to smem (A transposed to [k][m], tf32-rounded)
        As[ac + 0][ar] = f2tf32(aReg0.x);
        As[ac + 1][ar] = f2tf32(aReg0.y);
        As[ac + 2][ar] = f2tf32(aReg0.z);
        As[ac + 3][ar] = f2tf32(aReg0.w);
        As[ac + 4][ar] = f2tf32(aReg1.x);
        As[ac + 5][ar] = f2tf32(aReg1.y);
        As[ac + 6][ar] = f2tf32(aReg1.z);
        As[ac + 7][ar] = f2tf32(aReg1.w);
        uint4 bt;
        bt.x = f2tf32(bReg.x); bt.y = f2tf32(bReg.y);
        bt.z = f2tf32(bReg.z); bt.w = f2tf32(bReg.w);
        *(uint4*)(&Bs[br][bc]) = bt;
        __syncthreads();

        if (kt + 1 < KT) {
            int k0 = (kt + 1) * BKK;
            aReg0 = *(const float4*)(Abase + k0);
            aReg1 = *(const float4*)(Abase + k0 + 4);
            bReg  = *(const float4*)(Bbase + (size_t)k0 * FC);
        }

#pragma unroll
        for (int kk = 0; kk < BKK; kk += 8) {
            uint32_t a[2][4], b[4][2];
#pragma unroll
            for (int mi = 0; mi < 2; mi++) {
                int m = wm * 32 + mi * 16 + gid;
                a[mi][0] = As[kk + tig][m];
                a[mi][1] = As[kk + tig][m + 8];
                a[mi][2] = As[kk + tig + 4][m];
                a[mi][3] = As[kk + tig + 4][m + 8];
            }
#pragma unroll
            for (int ni = 0; ni < 4; ni++) {
                int nn = wn * 32 + ni * 8 + gid;
                b[ni][0] = Bs[kk + tig][nn];
                b[ni][1] = Bs[kk + tig + 4][nn];
            }
#pragma unroll
            for (int mi = 0; mi < 2; mi++)
#pragma unroll
                for (int ni = 0; ni < 4; ni++) {
                    asm volatile(
                        "mma.sync.aligned.m16n8k8.row.col.f32.tf32.tf32.f32 "
                        "{%0,%1,%2,%3}, {%4,%5,%6,%7}, {%8,%9}, {%0,%1,%2,%3};"
                        : "+f"(acc[mi][ni][0]), "+f"(acc[mi][ni][1]),
                          "+f"(acc[mi][ni][2]), "+f"(acc[mi][ni][3])
                        : "r"(a[mi][0]), "r"(a[mi][1]), "r"(a[mi][2]), "r"(a[mi][3]),
                          "r"(b[ni][0]), "r"(b[ni][1]));
                }
        }
        __syncthreads();
    }

    // epilogue: + bias, relu.  c0,c1 = (row, col), (row, col+1); c2,c3 = row+8
#pragma unroll
    for (int mi = 0; mi < 2; mi++) {
        int row = m0 + wm * 32 + mi * 16 + gid;
#pragma unroll
        for (int ni = 0; ni < 4; ni++) {
            int col = n0 + wn * 32 + ni * 8 + tig * 2;
            float bb0 = b1[col], bb1 = b1[col + 1];
            float2 v0, v1;
            v0.x = fmaxf(acc[mi][ni][0] + bb0, 0.0f);
            v0.y = fmaxf(acc[mi][ni][1] + bb1, 0.0f);
            v1.x = fmaxf(acc[mi][ni][2] + bb0, 0.0f);
            v1.y = fmaxf(acc[mi][ni][3] + bb1, 0.0f);
            *(float2*)(g_hid + (size_t)row * FC + col) = v0;
            *(float2*)(g_hid + (size_t)(row + 8) * FC + col) = v1;
        }
    }
}

// ---------------- kernel 4: GEMM2 + sigmoid ----------------------------------
// 4 rois per block, 256 threads: thread = (roi r = t>>6, out o = t&63, o<49).
__global__ void __launch_bounds__(256) gemm2_kernel(const float* __restrict__ w2,
                                                    const float* __restrict__ b2) {
    __shared__ float sh[4][FC];
    int n0 = blockIdx.x * 4;
    int tid = threadIdx.x;

    // load 4 hid rows: 4*1024 floats = 1024 float4, 4 per thread
    const float4* src = (const float4*)(g_hid + (size_t)n0 * FC);
    float4* dst = (float4*)(&sh[0][0]);
#pragma unroll
    for (int i = 0; i < 4; i++)
        dst[tid + 256 * i] = src[tid + 256 * i];
    __syncthreads();

    int r = tid >> 6;
    int o = tid & 63;
    if (o < NOUT) {
        float acc = b2[o];
        const float* hrow = sh[r];
#pragma unroll 8
        for (int k = 0; k < FC; k++)
            acc += hrow[k] * __ldg(w2 + k * NOUT + o);
        g_mask[(n0 + r) * NOUT + o] = 1.0f / (1.0f + expf(-acc));
    }
}

// ---------------- kernel 5: out = x * mask -----------------------------------
__global__ void modulate_kernel(float* __restrict__ out, int total) {
    int idx = blockIdx.x * blockDim.x + threadIdx.x;
    if (idx >= total) return;
    int n = idx / ICN;
    int rem = idx - n * ICN;
    int hw = rem % NOUT;
    out[idx] = g_x[idx] * g_mask[n * NOUT + hw];
}

// ---------------- launcher ---------------------------------------------------
extern "C" void kernel_launch(void* const* d_in, const int* in_sizes, int n_in,
                              void* d_out, int out_size) {
    const float* features = (const float*)d_in[0];
    const float* rois     = (const float*)d_in[1];
    const float* w1       = (const float*)d_in[2];
    const float* b1       = (const float*)d_in[3];
    const float* w2       = (const float*)d_in[4];
    const float* b2       = (const float*)d_in[5];
    float* out = (float*)d_out;

    transpose_kernel<<<dim3((HH * WW) / 32, CCH / 32, 2), dim3(32, 8)>>>(features);
    roi_kernel<<<NROI, 256>>>(rois);
    gemm1_kernel<<<dim3(FC / BN, NROI / BM), 256>>>(w1, b1);
    gemm2_kernel<<<NROI / 4, 256>>>(w2, b2);
    int total = NROI * ICN;
    modulate_kernel<<<(total + 255) / 256, 256>>>(out, total);
}

// round 3
// speedup vs baseline: 2.4241x; 2.0913x over previous
#include <cuda_runtime.h>
#include <cuda_bf16.h>
#include <math.h>
#include <stdint.h>

#define HH 256
#define WW 256
#define CCH 256
#define NROI 1024
#define ICN 12544          // 256 * 49
#define FC 1024
#define NOUT 49

// ---------------- scratch (device globals; no allocations allowed) ----------
__device__ float g_feat_t[(size_t)2 * 256 * 256 * 256];  // (B,H,W,C) 134MB
__device__ float g_x[(size_t)NROI * ICN];                // (n,C,7,7)  51MB fp32
__device__ __nv_bfloat16 g_xb[(size_t)NROI * ICN];       // bf16 copy  25MB
__device__ __nv_bfloat16 g_w1b[(size_t)ICN * FC];        // w1 bf16    25MB
__device__ float g_w2t[NOUT * FC];                       // w2 transposed
__device__ float g_hid[(size_t)NROI * FC];               // 4MB
__device__ float g_mask[NROI * NOUT];

__device__ __forceinline__ uint32_t smem_u32(const void* p) {
    return (uint32_t)__cvta_generic_to_shared(p);
}
__device__ __forceinline__ void cp_async16(uint32_t dst, const void* src) {
    asm volatile("cp.async.cg.shared.global [%0], [%1], 16;\n" :: "r"(dst), "l"(src));
}
#define CP_COMMIT() asm volatile("cp.async.commit_group;\n")
#define CP_WAIT(n)  asm volatile("cp.async.wait_group %0;\n" :: "n"(n))

// ---------------- kernel 1: transpose (B,C,H,W) -> (B,H,W,C) -----------------
__global__ void transpose_kernel(const float* __restrict__ f) {
    __shared__ float tile[32][33];
    int b = blockIdx.z;
    int hw0 = blockIdx.x * 32;
    int c0 = blockIdx.y * 32;
    int tx = threadIdx.x, ty = threadIdx.y;
    const float* src = f + ((size_t)b * CCH) * (HH * WW);
#pragma unroll
    for (int i = 0; i < 32; i += 8)
        tile[ty + i][tx] = src[(size_t)(c0 + ty + i) * (HH * WW) + hw0 + tx];
    __syncthreads();
    float* dst = g_feat_t + ((size_t)b << 24);
#pragma unroll
    for (int i = 0; i < 32; i += 8)
        dst[(size_t)(hw0 + ty + i) * CCH + c0 + tx] = tile[tx][ty + i];
}

// ---------------- conversions ------------------------------------------------
__global__ void conv_w1_kernel(const float* __restrict__ w1) {
    size_t i = (size_t)blockIdx.x * 256 + threadIdx.x;   // one uint4 (8 bf16) each
    const float4* s = (const float4*)w1 + i * 2;
    float4 a = s[0], b = s[1];
    __nv_bfloat162 p0 = __nv_bfloat162(__float2bfloat16(a.x), __float2bfloat16(a.y));
    __nv_bfloat162 p1 = __nv_bfloat162(__float2bfloat16(a.z), __float2bfloat16(a.w));
    __nv_bfloat162 p2 = __nv_bfloat162(__float2bfloat16(b.x), __float2bfloat16(b.y));
    __nv_bfloat162 p3 = __nv_bfloat162(__float2bfloat16(b.z), __float2bfloat16(b.w));
    uint4 out;
    out.x = *(uint32_t*)&p0; out.y = *(uint32_t*)&p1;
    out.z = *(uint32_t*)&p2; out.w = *(uint32_t*)&p3;
    ((uint4*)g_w1b)[i] = out;
}

__global__ void conv_w2_kernel(const float* __restrict__ w2) {
    int i = blockIdx.x * 256 + threadIdx.x;
    if (i < FC * NOUT) {
        int k = i / NOUT, o = i - k * NOUT;
        g_w2t[o * FC + k] = w2[i];
    }
}

// ---------------- kernel 2: rotated roi-align --------------------------------
struct alignas(16) Samp { int yl, xl, yh, xh; float w11, w12, w21, w22; };

__global__ void __launch_bounds__(256) roi_kernel(const float* __restrict__ rois) {
    __shared__ Samp samp[196];
    __shared__ float tile[25][257];
    int n = blockIdx.x;
    int tid = threadIdx.x;

    const float* r = rois + n * 6;
    int b = (int)r[0];
    float cx = r[1] * 0.125f;
    float cy = r[2] * 0.125f;
    float rw = fmaxf(r[3] * 0.125f, 1.0f);
    float rh = fmaxf(r[4] * 0.125f, 1.0f);
    float theta = r[5];
    float st, ct;
    sincosf(theta, &st, &ct);
    float bw = rw / 7.0f;
    float bh = rh / 7.0f;

    if (tid < 196) {
        int bin = tid >> 2;
        int s = tid & 3;
        int ph = bin / 7, pw = bin - ph * 7;
        int sy = s >> 1, sx = s & 1;
        float yy = -rh * 0.5f + ((float)ph + 0.25f + 0.5f * (float)sy) * bh;
        float xx = -rw * 0.5f + ((float)pw + 0.25f + 0.5f * (float)sx) * bw;
        float xs = xx * ct - yy * st + cx;
        float ys = xx * st + yy * ct + cy;
        bool valid = (ys > -1.0f) && (ys < (float)HH) && (xs > -1.0f) && (xs < (float)WW);
        float ysc = fminf(fmaxf(ys, 0.0f), (float)(HH - 1));
        float xsc = fminf(fmaxf(xs, 0.0f), (float)(WW - 1));
        int yl = (int)floorf(ysc);
        int xl = (int)floorf(xsc);
        int yh = min(yl + 1, HH - 1);
        int xh = min(xl + 1, WW - 1);
        float ly = ysc - (float)yl;
        float lx = xsc - (float)xl;
        float hy = 1.0f - ly, hx = 1.0f - lx;
        float vf = valid ? 0.25f : 0.0f;
        Samp sp;
        sp.yl = yl; sp.xl = xl; sp.yh = yh; sp.xh = xh;
        sp.w11 = hy * hx * vf; sp.w12 = hy * lx * vf;
        sp.w21 = ly * hx * vf; sp.w22 = ly * lx * vf;
        samp[tid] = sp;
    }
    __syncthreads();

    const float* ft = g_feat_t + ((size_t)b << 24) + tid;
    float* xo = g_x + (size_t)n * ICN;
    __nv_bfloat16* xb = g_xb + (size_t)n * ICN;

#pragma unroll 1
    for (int bl = 0; bl < 25; bl++) {
        float acc = 0.0f;
#pragma unroll
        for (int s = 0; s < 4; s++) {
            const Samp* sp = &samp[bl * 4 + s];
            int4 id = *(const int4*)(&sp->yl);
            float4 w = *(const float4*)(&sp->w11);
            int rl = id.x << 16, ch = id.w << 8;
            int rh2 = id.z << 16, cl = id.y << 8;
            float v11 = ft[rl + cl];
            float v12 = ft[rl + ch];
            float v21 = ft[rh2 + cl];
            float v22 = ft[rh2 + ch];
            acc += w.x * v11 + w.y * v12 + w.z * v21 + w.w * v22;
        }
        tile[bl][tid] = acc;
    }
    __syncthreads();
    for (int i = tid; i < 256 * 25; i += 256) {
        int c = i / 25;
        int hwl = i - c * 25;
        float v = tile[hwl][c];
        xo[c * 49 + hwl] = v;
        xb[c * 49 + hwl] = __float2bfloat16(v);
    }
    __syncthreads();

#pragma unroll 1
    for (int bl = 0; bl < 24; bl++) {
        int bin = 25 + bl;
        float acc = 0.0f;
#pragma unroll
        for (int s = 0; s < 4; s++) {
            const Samp* sp = &samp[bin * 4 + s];
            int4 id = *(const int4*)(&sp->yl);
            float4 w = *(const float4*)(&sp->w11);
            int rl = id.x << 16, ch = id.w << 8;
            int rh2 = id.z << 16, cl = id.y << 8;
            float v11 = ft[rl + cl];
            float v12 = ft[rl + ch];
            float v21 = ft[rh2 + cl];
            float v22 = ft[rh2 + ch];
            acc += w.x * v11 + w.y * v12 + w.z * v21 + w.w * v22;
        }
        tile[bl][tid] = acc;
    }
    __syncthreads();
    for (int i = tid; i < 256 * 24; i += 256) {
        int c = i / 24;
        int hwl = i - c * 24;
        float v = tile[hwl][c];
        xo[c * 49 + 25 + hwl] = v;
        xb[c * 49 + 25 + hwl] = __float2bfloat16(v);
    }
}

// ---------------- kernel 3: GEMM1 hid = relu(x @ w1 + b1), bf16 HMMA ---------
// M=1024, N=1024, K=12544. BM=128, BN=64, BK=64, 256 threads (8 warps 4x2),
// warp tile 32x32, cp.async double buffer, ldmatrix + XOR-swizzled 128B rows.
#define BM 128
#define BN 64
#define BK 64
#define KT (ICN / BK)   // 196

__device__ __forceinline__ void ldmatrix_x4(uint32_t* r, uint32_t addr) {
    asm volatile("ldmatrix.sync.aligned.m8n8.x4.shared.b16 {%0,%1,%2,%3}, [%4];"
                 : "=r"(r[0]), "=r"(r[1]), "=r"(r[2]), "=r"(r[3]) : "r"(addr));
}
__device__ __forceinline__ void ldmatrix_x4_trans(uint32_t* r, uint32_t addr) {
    asm volatile("ldmatrix.sync.aligned.m8n8.x4.trans.shared.b16 {%0,%1,%2,%3}, [%4];"
                 : "=r"(r[0]), "=r"(r[1]), "=r"(r[2]), "=r"(r[3]) : "r"(addr));
}

__global__ void __launch_bounds__(256) gemm1_kernel(const float* __restrict__ b1) {
    __shared__ __align__(128) uint8_t sm[49152];
    uint8_t* sA = sm;            // [2][128 rows][128 B]  (64 bf16/row)
    uint8_t* sB = sm + 32768;    // [2][64 rows][128 B]

    int t = threadIdx.x;
    int lane = t & 31, warp = t >> 5;
    int wm = warp >> 1, wn = warp & 1;
    int n0 = blockIdx.x * BN;
    int m0 = blockIdx.y * BM;

    // ---- staging roles ----
    int am = t & 127, ah = t >> 7;     // A: row am, 64B half ah (4 x cp.async16)
    const uint8_t* agp = (const uint8_t*)(g_xb + (size_t)(m0 + am) * ICN) + ah * 64;
    uint32_t aSm[4];
#pragma unroll
    for (int j = 0; j < 4; j++) {
        int q = ah * 4 + j;
        aSm[j] = smem_u32(sA + am * 128 + ((q ^ (am & 7)) << 4));
    }
    int bkr = t >> 2, bq0 = (t & 3) * 2;  // B: row bkr, chunks bq0, bq0+1
    const uint8_t* bgp = (const uint8_t*)(g_w1b + (size_t)bkr * FC + n0) + bq0 * 16;
    uint32_t bSm[2];
#pragma unroll
    for (int j = 0; j < 2; j++) {
        int q = bq0 + j;
        bSm[j] = smem_u32(sB + bkr * 128 + ((q ^ (bkr & 7)) << 4));
    }
    const size_t bStepG = (size_t)BK * FC * 2;   // bytes per k-tile of w1b

    // ---- compute roles ----
    int mRow0 = wm * 32 + (lane & 15);           // mi adds 16 (doesn't change &7)
    int msw = mRow0 & 7;
    int aQsel = lane >> 4;
    uint32_t aBase0 = smem_u32(sA + mRow0 * 128);
    uint32_t aBase1 = aBase0 + 16 * 128;
    int bK = lane & 15;
    uint32_t bBase = smem_u32(sB + bK * 128);
    int physB0 = (wn * 4 + 0 + (lane >> 4)) ^ (bK & 7);
    int physB1 = (wn * 4 + 2 + (lane >> 4)) ^ (bK & 7);

    float acc[2][4][4];
#pragma unroll
    for (int mi = 0; mi < 2; mi++)
#pragma unroll
        for (int ni = 0; ni < 4; ni++)
#pragma unroll
            for (int j = 0; j < 4; j++) acc[mi][ni][j] = 0.0f;

    // prologue: stage 0
    {
        const uint8_t* ag = agp;
#pragma unroll
        for (int j = 0; j < 4; j++) cp_async16(aSm[j], ag + j * 16);
        const uint8_t* bg = bgp;
#pragma unroll
        for (int j = 0; j < 2; j++) cp_async16(bSm[j], bg + j * 16);
        CP_COMMIT();
    }

    for (int kt = 0; kt < KT; kt++) {
        int buf = kt & 1;
        if (kt + 1 < KT) {
            uint32_t ao = (buf ^ 1) * 16384, bo = (buf ^ 1) * 8192;
            const uint8_t* ag = agp + (size_t)(kt + 1) * 128;
#pragma unroll
            for (int j = 0; j < 4; j++) cp_async16(aSm[j] + ao, ag + j * 16);
            const uint8_t* bg = bgp + (size_t)(kt + 1) * bStepG;
#pragma unroll
            for (int j = 0; j < 2; j++) cp_async16(bSm[j] + bo, bg + j * 16);
            CP_COMMIT();
            CP_WAIT(1);
        } else {
            CP_WAIT(0);
        }
        __syncthreads();

        uint32_t ao = buf * 16384, bo = buf * 8192;
#pragma unroll
        for (int kk = 0; kk < BK; kk += 16) {
            uint32_t a[2][4], b[2][4];
            int qa = (kk >> 3) + aQsel;
            uint32_t aoff = ao + (uint32_t)(((qa ^ msw)) << 4);
            ldmatrix_x4(a[0], aBase0 + aoff);
            ldmatrix_x4(a[1], aBase1 + aoff);
            uint32_t boff = bo + (uint32_t)((kk + 0) * 128);
            ldmatrix_x4_trans(b[0], bBase + boff + (physB0 << 4));
            ldmatrix_x4_trans(b[1], bBase + boff + (physB1 << 4));
#pragma unroll
            for (int mi = 0; mi < 2; mi++)
#pragma unroll
                for (int ni = 0; ni < 4; ni++) {
                    uint32_t bb0 = b[ni >> 1][(ni & 1) * 2];
                    uint32_t bb1 = b[ni >> 1][(ni & 1) * 2 + 1];
                    asm volatile(
                        "mma.sync.aligned.m16n8k16.row.col.f32.bf16.bf16.f32 "
                        "{%0,%1,%2,%3}, {%4,%5,%6,%7}, {%8,%9}, {%0,%1,%2,%3};"
                        : "+f"(acc[mi][ni][0]), "+f"(acc[mi][ni][1]),
                          "+f"(acc[mi][ni][2]), "+f"(acc[mi][ni][3])
                        : "r"(a[mi][0]), "r"(a[mi][1]), "r"(a[mi][2]), "r"(a[mi][3]),
                          "r"(bb0), "r"(bb1));
                }
        }
        __syncthreads();
    }

    // epilogue: + bias, relu
    int tig = lane & 3;
    int gid = lane >> 2;
#pragma unroll
    for (int mi = 0; mi < 2; mi++) {
        int row = m0 + wm * 32 + mi * 16 + gid;
#pragma unroll
        for (int ni = 0; ni < 4; ni++) {
            int col = n0 + wn * 32 + ni * 8 + tig * 2;
            float bb0 = b1[col], bb1 = b1[col + 1];
            float2 v0, v1;
            v0.x = fmaxf(acc[mi][ni][0] + bb0, 0.0f);
            v0.y = fmaxf(acc[mi][ni][1] + bb1, 0.0f);
            v1.x = fmaxf(acc[mi][ni][2] + bb0, 0.0f);
            v1.y = fmaxf(acc[mi][ni][3] + bb1, 0.0f);
            *(float2*)(g_hid + (size_t)row * FC + col) = v0;
            *(float2*)(g_hid + (size_t)(row + 8) * FC + col) = v1;
        }
    }
}

// ---------------- kernel 4: GEMM2 + sigmoid ----------------------------------
// 2 rois/block, warp-per-output, shfl reduce; w2t rows are coalesced float4.
__global__ void __launch_bounds__(256) gemm2_kernel(const float* __restrict__ b2) {
    __shared__ float sh[2][FC];
    int n0 = blockIdx.x * 2;
    int tid = threadIdx.x;

    float4* d = (float4*)&sh[0][0];
    const float4* s = (const float4*)(g_hid + (size_t)n0 * FC);
    d[tid] = s[tid];
    d[tid + 256] = s[tid + 256];
    __syncthreads();

    int warp = tid >> 5, lane = tid & 31;
    const float4* h0 = (const float4*)sh[0];
    const float4* h1 = (const float4*)sh[1];
    for (int o = warp; o < NOUT; o += 8) {
        const float4* wr = (const float4*)(g_w2t + (size_t)o * FC);
        float a0 = 0.0f, a1 = 0.0f;
#pragma unroll
        for (int i = 0; i < 8; i++) {
            float4 w = wr[i * 32 + lane];
            float4 x0 = h0[i * 32 + lane];
            float4 x1 = h1[i * 32 + lane];
            a0 += w.x * x0.x + w.y * x0.y + w.z * x0.z + w.w * x0.w;
            a1 += w.x * x1.x + w.y * x1.y + w.z * x1.z + w.w * x1.w;
        }
#pragma unroll
        for (int off = 16; off > 0; off >>= 1) {
            a0 += __shfl_xor_sync(0xffffffffu, a0, off);
            a1 += __shfl_xor_sync(0xffffffffu, a1, off);
        }
        if (lane == 0) {
            float bb = b2[o];
            g_mask[n0 * NOUT + o] = 1.0f / (1.0f + expf(-(a0 + bb)));
            g_mask[(n0 + 1) * NOUT + o] = 1.0f / (1.0f + expf(-(a1 + bb)));
        }
    }
}

// ---------------- kernel 5: out = x * mask -----------------------------------
__global__ void modulate_kernel(float* __restrict__ out, int total) {
    int idx = blockIdx.x * blockDim.x + threadIdx.x;
    if (idx >= total) return;
    int n = idx / ICN;
    int rem = idx - n * ICN;
    int hw = rem % NOUT;
    out[idx] = g_x[idx] * g_mask[n * NOUT + hw];
}

// ---------------- launcher ---------------------------------------------------
extern "C" void kernel_launch(void* const* d_in, const int* in_sizes, int n_in,
                              void* d_out, int out_size) {
    const float* features = (const float*)d_in[0];
    const float* rois     = (const float*)d_in[1];
    const float* w1       = (const float*)d_in[2];
    const float* b1       = (const float*)d_in[3];
    const float* w2       = (const float*)d_in[4];
    const float* b2       = (const float*)d_in[5];
    float* out = (float*)d_out;

    transpose_kernel<<<dim3((HH * WW) / 32, CCH / 32, 2), dim3(32, 8)>>>(features);
    conv_w1_kernel<<<(ICN * FC / 8) / 256, 256>>>(w1);
    conv_w2_kernel<<<(FC * NOUT + 255) / 256, 256>>>(w2);
    roi_kernel<<<NROI, 256>>>(rois);
    gemm1_kernel<<<dim3(FC / BN, NROI / BM), 256>>>(b1);
    gemm2_kernel<<<NROI / 2, 256>>>(b2);
    int total = NROI * ICN;
    modulate_kernel<<<(total + 255) / 256, 256>>>(out, total);
}

// round 4
// speedup vs baseline: 2.6146x; 1.0786x over previous
#include <cuda_runtime.h>
#include <cuda_bf16.h>
#include <math.h>
#include <stdint.h>

#define HH 256
#define WW 256
#define CCH 256
#define NROI 1024
#define ICN 12544          // 256 * 49
#define FC 1024
#define NOUT 49

// ---------------- scratch (device globals; no allocations allowed) ----------
__device__ float g_feat_t[(size_t)2 * 256 * 256 * 256];  // (B,H,W,C) 134MB
__device__ float g_x[(size_t)NROI * ICN];                // (n,HW,C)  51MB fp32
__device__ __nv_bfloat16 g_xb[(size_t)NROI * ICN];       // bf16 copy (n,HW,C)
__device__ __nv_bfloat16 g_w1b[(size_t)ICN * FC];        // w1 bf16, K-permuted
__device__ float g_w2t[NOUT * FC];                       // w2 transposed
__device__ float g_hid[(size_t)NROI * FC];               // 4MB
__device__ float g_mask[NROI * NOUT];

__device__ __forceinline__ uint32_t smem_u32(const void* p) {
    return (uint32_t)__cvta_generic_to_shared(p);
}
__device__ __forceinline__ void cp_async16(uint32_t dst, const void* src) {
    asm volatile("cp.async.cg.shared.global [%0], [%1], 16;\n" :: "r"(dst), "l"(src));
}
#define CP_COMMIT() asm volatile("cp.async.commit_group;\n")
#define CP_WAIT(n)  asm volatile("cp.async.wait_group %0;\n" :: "n"(n))

// ---------------- kernel 1: transpose (B,C,H,W) -> (B,H,W,C), float4 ---------
__global__ void __launch_bounds__(256) transpose_kernel(const float* __restrict__ f) {
    __shared__ float tile[32][33];
    int b = blockIdx.z;
    int hw0 = blockIdx.x * 32;
    int c0 = blockIdx.y * 32;
    int t = threadIdx.x;

    // load: ty = channel row, tx = hw float4
    int ty = t >> 3, tx = t & 7;
    const float* src = f + ((size_t)b * CCH + c0 + ty) * (HH * WW) + hw0 + tx * 4;
    float4 v = *(const float4*)src;
    tile[tx * 4 + 0][ty] = v.x;
    tile[tx * 4 + 1][ty] = v.y;
    tile[tx * 4 + 2][ty] = v.z;
    tile[tx * 4 + 3][ty] = v.w;
    __syncthreads();

    // store: r = hw row, q = channel float4
    int r = t >> 3, q = t & 7;
    float4 o;
    o.x = tile[r][q * 4 + 0];
    o.y = tile[r][q * 4 + 1];
    o.z = tile[r][q * 4 + 2];
    o.w = tile[r][q * 4 + 3];
    float* dst = g_feat_t + ((size_t)b << 24) + (size_t)(hw0 + r) * CCH + c0 + q * 4;
    *(float4*)dst = o;
}

// ---------------- conversions ------------------------------------------------
// w1 bf16 + K-permutation: old row k = c*49+hw  ->  new row k' = hw*256+c
__global__ void __launch_bounds__(256) conv_w1_kernel(const float* __restrict__ w1) {
    size_t i = (size_t)blockIdx.x * 256 + threadIdx.x;   // one uint4 (8 bf16)
    int row = (int)(i >> 7);          // FC/8 = 128 chunks per row
    int col8 = (int)(i & 127);
    int c = row / 49, hw = row - c * 49;
    int nrow = hw * 256 + c;
    const float4* s = (const float4*)(w1 + (size_t)row * FC + col8 * 8);
    float4 a = s[0], bq = s[1];
    __nv_bfloat162 p0 = __nv_bfloat162(__float2bfloat16(a.x), __float2bfloat16(a.y));
    __nv_bfloat162 p1 = __nv_bfloat162(__float2bfloat16(a.z), __float2bfloat16(a.w));
    __nv_bfloat162 p2 = __nv_bfloat162(__float2bfloat16(bq.x), __float2bfloat16(bq.y));
    __nv_bfloat162 p3 = __nv_bfloat162(__float2bfloat16(bq.z), __float2bfloat16(bq.w));
    uint4 out;
    out.x = *(uint32_t*)&p0; out.y = *(uint32_t*)&p1;
    out.z = *(uint32_t*)&p2; out.w = *(uint32_t*)&p3;
    *(uint4*)(g_w1b + (size_t)nrow * FC + col8 * 8) = out;
}

__global__ void conv_w2_kernel(const float* __restrict__ w2) {
    int i = blockIdx.x * 256 + threadIdx.x;
    if (i < FC * NOUT) {
        int k = i / NOUT, o = i - k * NOUT;
        g_w2t[o * FC + k] = w2[i];
    }
}

// ---------------- kernel 2: rotated roi-align --------------------------------
struct alignas(16) Samp { int yl, xl, yh, xh; float w11, w12, w21, w22; };

__global__ void __launch_bounds__(256, 5) roi_kernel(const float* __restrict__ rois) {
    __shared__ Samp samp[196];
    int n = blockIdx.x;
    int tid = threadIdx.x;

    const float* r = rois + n * 6;
    int b = (int)r[0];
    float cx = r[1] * 0.125f;
    float cy = r[2] * 0.125f;
    float rw = fmaxf(r[3] * 0.125f, 1.0f);
    float rh = fmaxf(r[4] * 0.125f, 1.0f);
    float theta = r[5];
    float st, ct;
    sincosf(theta, &st, &ct);
    float bw = rw / 7.0f;
    float bh = rh / 7.0f;

    if (tid < 196) {
        int bin = tid >> 2;
        int s = tid & 3;
        int ph = bin / 7, pw = bin - ph * 7;
        int sy = s >> 1, sx = s & 1;
        float yy = -rh * 0.5f + ((float)ph + 0.25f + 0.5f * (float)sy) * bh;
        float xx = -rw * 0.5f + ((float)pw + 0.25f + 0.5f * (float)sx) * bw;
        float xs = xx * ct - yy * st + cx;
        float ys = xx * st + yy * ct + cy;
        bool valid = (ys > -1.0f) && (ys < (float)HH) && (xs > -1.0f) && (xs < (float)WW);
        float ysc = fminf(fmaxf(ys, 0.0f), (float)(HH - 1));
        float xsc = fminf(fmaxf(xs, 0.0f), (float)(WW - 1));
        int yl = (int)floorf(ysc);
        int xl = (int)floorf(xsc);
        int yh = min(yl + 1, HH - 1);
        int xh = min(xl + 1, WW - 1);
        float ly = ysc - (float)yl;
        float lx = xsc - (float)xl;
        float hy = 1.0f - ly, hx = 1.0f - lx;
        float vf = valid ? 0.25f : 0.0f;
        Samp sp;
        sp.yl = yl; sp.xl = xl; sp.yh = yh; sp.xh = xh;
        sp.w11 = hy * hx * vf; sp.w12 = hy * lx * vf;
        sp.w21 = ly * hx * vf; sp.w22 = ly * lx * vf;
        samp[tid] = sp;
    }
    __syncthreads();

    const float* ft = g_feat_t + ((size_t)b << 24) + tid;
    float* xo = g_x + (size_t)n * ICN;               // (hw, c): direct coalesced
    __nv_bfloat16* xb = g_xb + (size_t)n * ICN;

#pragma unroll 1
    for (int bl = 0; bl < 48; bl += 2) {
        float acc0 = 0.0f, acc1 = 0.0f;
#pragma unroll
        for (int s = 0; s < 4; s++) {
            const Samp* sp0 = &samp[bl * 4 + s];
            const Samp* sp1 = &samp[bl * 4 + 4 + s];
            int4 i0 = *(const int4*)(&sp0->yl);
            float4 w0 = *(const float4*)(&sp0->w11);
            int4 i1 = *(const int4*)(&sp1->yl);
            float4 w1_ = *(const float4*)(&sp1->w11);
            float a11 = ft[(i0.x << 16) + (i0.y << 8)];
            float a12 = ft[(i0.x << 16) + (i0.w << 8)];
            float a21 = ft[(i0.z << 16) + (i0.y << 8)];
            float a22 = ft[(i0.z << 16) + (i0.w << 8)];
            float b11 = ft[(i1.x << 16) + (i1.y << 8)];
            float b12 = ft[(i1.x << 16) + (i1.w << 8)];
            float b21 = ft[(i1.z << 16) + (i1.y << 8)];
            float b22 = ft[(i1.z << 16) + (i1.w << 8)];
            acc0 += w0.x * a11 + w0.y * a12 + w0.z * a21 + w0.w * a22;
            acc1 += w1_.x * b11 + w1_.y * b12 + w1_.z * b21 + w1_.w * b22;
        }
        xo[bl * 256 + tid] = acc0;
        xo[(bl + 1) * 256 + tid] = acc1;
        xb[bl * 256 + tid] = __float2bfloat16(acc0);
        xb[(bl + 1) * 256 + tid] = __float2bfloat16(acc1);
    }
    {   // bin 48
        float acc = 0.0f;
#pragma unroll
        for (int s = 0; s < 4; s++) {
            const Samp* sp = &samp[48 * 4 + s];
            int4 id = *(const int4*)(&sp->yl);
            float4 w = *(const float4*)(&sp->w11);
            acc += w.x * ft[(id.x << 16) + (id.y << 8)]
                 + w.y * ft[(id.x << 16) + (id.w << 8)]
                 + w.z * ft[(id.z << 16) + (id.y << 8)]
                 + w.w * ft[(id.z << 16) + (id.w << 8)];
        }
        xo[48 * 256 + tid] = acc;
        xb[48 * 256 + tid] = __float2bfloat16(acc);
    }
}

// ---------------- kernel 3: GEMM1 hid = relu(x @ w1 + b1), bf16 HMMA ---------
#define BM 128
#define BN 64
#define BK 64
#define KT (ICN / BK)   // 196

__device__ __forceinline__ void ldmatrix_x4(uint32_t* r, uint32_t addr) {
    asm volatile("ldmatrix.sync.aligned.m8n8.x4.shared.b16 {%0,%1,%2,%3}, [%4];"
                 : "=r"(r[0]), "=r"(r[1]), "=r"(r[2]), "=r"(r[3]) : "r"(addr));
}
__device__ __forceinline__ void ldmatrix_x4_trans(uint32_t* r, uint32_t addr) {
    asm volatile("ldmatrix.sync.aligned.m8n8.x4.trans.shared.b16 {%0,%1,%2,%3}, [%4];"
                 : "=r"(r[0]), "=r"(r[1]), "=r"(r[2]), "=r"(r[3]) : "r"(addr));
}

__global__ void __launch_bounds__(256) gemm1_kernel(const float* __restrict__ b1) {
    __shared__ __align__(128) uint8_t sm[49152];
    uint8_t* sA = sm;            // [2][128 rows][128 B]
    uint8_t* sB = sm + 32768;    // [2][64 rows][128 B]

    int t = threadIdx.x;
    int lane = t & 31, warp = t >> 5;
    int wm = warp >> 1, wn = warp & 1;
    int n0 = blockIdx.x * BN;
    int m0 = blockIdx.y * BM;

    int am = t & 127, ah = t >> 7;
    const uint8_t* agp = (const uint8_t*)(g_xb + (size_t)(m0 + am) * ICN) + ah * 64;
    uint32_t aSm[4];
#pragma unroll
    for (int j = 0; j < 4; j++) {
        int q = ah * 4 + j;
        aSm[j] = smem_u32(sA + am * 128 + ((q ^ (am & 7)) << 4));
    }
    int bkr = t >> 2, bq0 = (t & 3) * 2;
    const uint8_t* bgp = (const uint8_t*)(g_w1b + (size_t)bkr * FC + n0) + bq0 * 16;
    uint32_t bSm[2];
#pragma unroll
    for (int j = 0; j < 2; j++) {
        int q = bq0 + j;
        bSm[j] = smem_u32(sB + bkr * 128 + ((q ^ (bkr & 7)) << 4));
    }
    const size_t bStepG = (size_t)BK * FC * 2;

    int mRow0 = wm * 32 + (lane & 15);
    int msw = mRow0 & 7;
    int aQsel = lane >> 4;
    uint32_t aBase0 = smem_u32(sA + mRow0 * 128);
    uint32_t aBase1 = aBase0 + 16 * 128;
    int bK = lane & 15;
    uint32_t bBase = smem_u32(sB + bK * 128);
    int physB0 = (wn * 4 + 0 + (lane >> 4)) ^ (bK & 7);
    int physB1 = (wn * 4 + 2 + (lane >> 4)) ^ (bK & 7);

    float acc[2][4][4];
#pragma unroll
    for (int mi = 0; mi < 2; mi++)
#pragma unroll
        for (int ni = 0; ni < 4; ni++)
#pragma unroll
            for (int j = 0; j < 4; j++) acc[mi][ni][j] = 0.0f;

    {
#pragma unroll
        for (int j = 0; j < 4; j++) cp_async16(aSm[j], agp + j * 16);
#pragma unroll
        for (int j = 0; j < 2; j++) cp_async16(bSm[j], bgp + j * 16);
        CP_COMMIT();
    }

    for (int kt = 0; kt < KT; kt++) {
        int buf = kt & 1;
        if (kt + 1 < KT) {
            uint32_t ao = (buf ^ 1) * 16384, bo = (buf ^ 1) * 8192;
            const uint8_t* ag = agp + (size_t)(kt + 1) * 128;
#pragma unroll
            for (int j = 0; j < 4; j++) cp_async16(aSm[j] + ao, ag + j * 16);
            const uint8_t* bg = bgp + (size_t)(kt + 1) * bStepG;
#pragma unroll
            for (int j = 0; j < 2; j++) cp_async16(bSm[j] + bo, bg + j * 16);
            CP_COMMIT();
            CP_WAIT(1);
        } else {
            CP_WAIT(0);
        }
        __syncthreads();

        uint32_t ao = buf * 16384, bo = buf * 8192;
#pragma unroll
        for (int kk = 0; kk < BK; kk += 16) {
            uint32_t a[2][4], b[2][4];
            int qa = (kk >> 3) + aQsel;
            uint32_t aoff = ao + (uint32_t)(((qa ^ msw)) << 4);
            ldmatrix_x4(a[0], aBase0 + aoff);
            ldmatrix_x4(a[1], aBase1 + aoff);
            uint32_t boff = bo + (uint32_t)(kk * 128);
            ldmatrix_x4_trans(b[0], bBase + boff + (physB0 << 4));
            ldmatrix_x4_trans(b[1], bBase + boff + (physB1 << 4));
#pragma unroll
            for (int mi = 0; mi < 2; mi++)
#pragma unroll
                for (int ni = 0; ni < 4; ni++) {
                    uint32_t bb0 = b[ni >> 1][(ni & 1) * 2];
                    uint32_t bb1 = b[ni >> 1][(ni & 1) * 2 + 1];
                    asm volatile(
                        "mma.sync.aligned.m16n8k16.row.col.f32.bf16.bf16.f32 "
                        "{%0,%1,%2,%3}, {%4,%5,%6,%7}, {%8,%9}, {%0,%1,%2,%3};"
                        : "+f"(acc[mi][ni][0]), "+f"(acc[mi][ni][1]),
                          "+f"(acc[mi][ni][2]), "+f"(acc[mi][ni][3])
                        : "r"(a[mi][0]), "r"(a[mi][1]), "r"(a[mi][2]), "r"(a[mi][3]),
                          "r"(bb0), "r"(bb1));
                }
        }
        __syncthreads();
    }

    int tig = lane & 3;
    int gid = lane >> 2;
#pragma unroll
    for (int mi = 0; mi < 2; mi++) {
        int row = m0 + wm * 32 + mi * 16 + gid;
#pragma unroll
        for (int ni = 0; ni < 4; ni++) {
            int col = n0 + wn * 32 + ni * 8 + tig * 2;
            float bb0 = b1[col], bb1 = b1[col + 1];
            float2 v0, v1;
            v0.x = fmaxf(acc[mi][ni][0] + bb0, 0.0f);
            v0.y = fmaxf(acc[mi][ni][1] + bb1, 0.0f);
            v1.x = fmaxf(acc[mi][ni][2] + bb0, 0.0f);
            v1.y = fmaxf(acc[mi][ni][3] + bb1, 0.0f);
            *(float2*)(g_hid + (size_t)row * FC + col) = v0;
            *(float2*)(g_hid + (size_t)(row + 8) * FC + col) = v1;
        }
    }
}

// ---------------- kernel 4: GEMM2 + sigmoid ----------------------------------
__global__ void __launch_bounds__(256) gemm2_kernel(const float* __restrict__ b2) {
    __shared__ float sh[2][FC];
    int n0 = blockIdx.x * 2;
    int tid = threadIdx.x;

    float4* d = (float4*)&sh[0][0];
    const float4* s = (const float4*)(g_hid + (size_t)n0 * FC);
    d[tid] = s[tid];
    d[tid + 256] = s[tid + 256];
    __syncthreads();

    int warp = tid >> 5, lane = tid & 31;
    const float4* h0 = (const float4*)sh[0];
    const float4* h1 = (const float4*)sh[1];
    for (int o = warp; o < NOUT; o += 8) {
        const float4* wr = (const float4*)(g_w2t + (size_t)o * FC);
        float a0 = 0.0f, a1 = 0.0f;
#pragma unroll
        for (int i = 0; i < 8; i++) {
            float4 w = wr[i * 32 + lane];
            float4 x0 = h0[i * 32 + lane];
            float4 x1 = h1[i * 32 + lane];
            a0 += w.x * x0.x + w.y * x0.y + w.z * x0.z + w.w * x0.w;
            a1 += w.x * x1.x + w.y * x1.y + w.z * x1.z + w.w * x1.w;
        }
#pragma unroll
        for (int off = 16; off > 0; off >>= 1) {
            a0 += __shfl_xor_sync(0xffffffffu, a0, off);
            a1 += __shfl_xor_sync(0xffffffffu, a1, off);
        }
        if (lane == 0) {
            float bb = b2[o];
            g_mask[n0 * NOUT + o] = 1.0f / (1.0f + expf(-(a0 + bb)));
            g_mask[(n0 + 1) * NOUT + o] = 1.0f / (1.0f + expf(-(a1 + bb)));
        }
    }
}

// ---------------- kernel 5: out(n,c,hw) = x(n,hw,c) * mask(n,hw) -------------
#define MPAD 261
__global__ void __launch_bounds__(256) modulate_kernel(float* __restrict__ out) {
    __shared__ float sh[25 * MPAD];
    __shared__ float msk[64];
    int n = blockIdx.x;
    int tid = threadIdx.x;
    if (tid < NOUT) msk[tid] = g_mask[n * NOUT + tid];

    const float* xs = g_x + (size_t)n * ICN;
    float* o = out + (size_t)n * ICN;

    // chunk 0: hw 0..24
    for (int i = tid; i < 25 * 256; i += 256) {
        int hw = i >> 8, c = i & 255;
        sh[hw * MPAD + c] = xs[i];
    }
    __syncthreads();
    for (int i = tid; i < 256 * 25; i += 256) {
        int c = i / 25, hw = i - c * 25;
        o[c * 49 + hw] = sh[hw * MPAD + c] * msk[hw];
    }
    __syncthreads();

    // chunk 1: hw 25..48
    for (int i = tid; i < 24 * 256; i += 256) {
        int hw = i >> 8, c = i & 255;
        sh[hw * MPAD + c] = xs[25 * 256 + i];
    }
    __syncthreads();
    for (int i = tid; i < 256 * 24; i += 256) {
        int c = i / 24, hw = i - c * 24;
        o[c * 49 + 25 + hw] = sh[hw * MPAD + c] * msk[25 + hw];
    }
}

// ---------------- launcher ---------------------------------------------------
extern "C" void kernel_launch(void* const* d_in, const int* in_sizes, int n_in,
                              void* d_out, int out_size) {
    const float* features = (const float*)d_in[0];
    const float* rois     = (const float*)d_in[1];
    const float* w1       = (const float*)d_in[2];
    const float* b1       = (const float*)d_in[3];
    const float* w2       = (const float*)d_in[4];
    const float* b2       = (const float*)d_in[5];
    float* out = (float*)d_out;

    transpose_kernel<<<dim3((HH * WW) / 32, CCH / 32, 2), 256>>>(features);
    conv_w1_kernel<<<(ICN * FC / 8) / 256, 256>>>(w1);
    conv_w2_kernel<<<(FC * NOUT + 255) / 256, 256>>>(w2);
    roi_kernel<<<NROI, 256>>>(rois);
    gemm1_kernel<<<dim3(FC / BN, NROI / BM), 256>>>(b1);
    gemm2_kernel<<<NROI / 2, 256>>>(b2);
    modulate_kernel<<<NROI, 256>>>(out);
}

// round 5
// speedup vs baseline: 3.1427x; 1.2020x over previous
#include <cuda_runtime.h>
#include <cuda_bf16.h>
#include <math.h>
#include <stdint.h>

#define HH 256
#define WW 256
#define CCH 256
#define NROI 1024
#define ICN 12544          // 256 * 49
#define FC 1024
#define NOUT 49
#define KSPLIT 4
#define KCH (ICN / KSPLIT)   // 3136

// ---------------- scratch (device globals; no allocations allowed) ----------
__device__ float g_feat_t[(size_t)2 * 256 * 256 * 256];  // (B,H,W,C) 134MB
__device__ float g_x[(size_t)NROI * ICN];                // (n,HW,C)  51MB fp32
__device__ __nv_bfloat16 g_xb[(size_t)NROI * ICN];       // bf16 copy (n,HW,C)
__device__ __nv_bfloat16 g_w1b[(size_t)ICN * FC];        // w1 bf16, K-permuted
__device__ float g_w2t[NOUT * FC];                       // w2 transposed
__device__ float g_part[KSPLIT][(size_t)NROI * FC];      // split-K partials 16MB
__device__ float g_hid[(size_t)NROI * FC];               // 4MB
__device__ float g_mask[NROI * NOUT];

__device__ __forceinline__ uint32_t smem_u32(const void* p) {
    return (uint32_t)__cvta_generic_to_shared(p);
}
__device__ __forceinline__ void cp_async16(uint32_t dst, const void* src) {
    asm volatile("cp.async.cg.shared.global [%0], [%1], 16;\n" :: "r"(dst), "l"(src));
}
#define CP_COMMIT() asm volatile("cp.async.commit_group;\n")
#define CP_WAIT(n)  asm volatile("cp.async.wait_group %0;\n" :: "n"(n))

// ---------------- kernel 1: transpose (B,C,H,W) -> (B,H,W,C), float4 ---------
__global__ void __launch_bounds__(256) transpose_kernel(const float* __restrict__ f) {
    __shared__ float tile[32][33];
    int b = blockIdx.z;
    int hw0 = blockIdx.x * 32;
    int c0 = blockIdx.y * 32;
    int t = threadIdx.x;

    int ty = t >> 3, tx = t & 7;
    const float* src = f + ((size_t)b * CCH + c0 + ty) * (HH * WW) + hw0 + tx * 4;
    float4 v = *(const float4*)src;
    tile[tx * 4 + 0][ty] = v.x;
    tile[tx * 4 + 1][ty] = v.y;
    tile[tx * 4 + 2][ty] = v.z;
    tile[tx * 4 + 3][ty] = v.w;
    __syncthreads();

    int r = t >> 3, q = t & 7;
    float4 o;
    o.x = tile[r][q * 4 + 0];
    o.y = tile[r][q * 4 + 1];
    o.z = tile[r][q * 4 + 2];
    o.w = tile[r][q * 4 + 3];
    float* dst = g_feat_t + ((size_t)b << 24) + (size_t)(hw0 + r) * CCH + c0 + q * 4;
    *(float4*)dst = o;
}

// ---------------- conversions ------------------------------------------------
// w1 bf16 + K-permutation: old row k = c*49+hw  ->  new row k' = hw*256+c
__global__ void __launch_bounds__(256) conv_w1_kernel(const float* __restrict__ w1) {
    size_t i = (size_t)blockIdx.x * 256 + threadIdx.x;
    int row = (int)(i >> 7);
    int col8 = (int)(i & 127);
    int c = row / 49, hw = row - c * 49;
    int nrow = hw * 256 + c;
    const float4* s = (const float4*)(w1 + (size_t)row * FC + col8 * 8);
    float4 a = s[0], bq = s[1];
    __nv_bfloat162 p0 = __nv_bfloat162(__float2bfloat16(a.x), __float2bfloat16(a.y));
    __nv_bfloat162 p1 = __nv_bfloat162(__float2bfloat16(a.z), __float2bfloat16(a.w));
    __nv_bfloat162 p2 = __nv_bfloat162(__float2bfloat16(bq.x), __float2bfloat16(bq.y));
    __nv_bfloat162 p3 = __nv_bfloat162(__float2bfloat16(bq.z), __float2bfloat16(bq.w));
    uint4 out;
    out.x = *(uint32_t*)&p0; out.y = *(uint32_t*)&p1;
    out.z = *(uint32_t*)&p2; out.w = *(uint32_t*)&p3;
    *(uint4*)(g_w1b + (size_t)nrow * FC + col8 * 8) = out;
}

__global__ void conv_w2_kernel(const float* __restrict__ w2) {
    int i = blockIdx.x * 256 + threadIdx.x;
    if (i < FC * NOUT) {
        int k = i / NOUT, o = i - k * NOUT;
        g_w2t[o * FC + k] = w2[i];
    }
}

// ---------------- kernel 2: rotated roi-align (2 blocks per roi) -------------
struct alignas(16) Samp { int yl, xl, yh, xh; float w11, w12, w21, w22; };

__global__ void __launch_bounds__(256, 5) roi_kernel(const float* __restrict__ rois) {
    __shared__ Samp samp[196];
    int n = blockIdx.x;
    int half = blockIdx.y;
    int tid = threadIdx.x;

    const float* r = rois + n * 6;
    int b = (int)r[0];
    float cx = r[1] * 0.125f;
    float cy = r[2] * 0.125f;
    float rw = fmaxf(r[3] * 0.125f, 1.0f);
    float rh = fmaxf(r[4] * 0.125f, 1.0f);
    float theta = r[5];
    float st, ct;
    sincosf(theta, &st, &ct);
    float bw = rw / 7.0f;
    float bh = rh / 7.0f;

    if (tid < 196) {
        int bin = tid >> 2;
        int s = tid & 3;
        int ph = bin / 7, pw = bin - ph * 7;
        int sy = s >> 1, sx = s & 1;
        float yy = -rh * 0.5f + ((float)ph + 0.25f + 0.5f * (float)sy) * bh;
        float xx = -rw * 0.5f + ((float)pw + 0.25f + 0.5f * (float)sx) * bw;
        float xs = xx * ct - yy * st + cx;
        float ys = xx * st + yy * ct + cy;
        bool valid = (ys > -1.0f) && (ys < (float)HH) && (xs > -1.0f) && (xs < (float)WW);
        float ysc = fminf(fmaxf(ys, 0.0f), (float)(HH - 1));
        float xsc = fminf(fmaxf(xs, 0.0f), (float)(WW - 1));
        int yl = (int)floorf(ysc);
        int xl = (int)floorf(xsc);
        int yh = min(yl + 1, HH - 1);
        int xh = min(xl + 1, WW - 1);
        float ly = ysc - (float)yl;
        float lx = xsc - (float)xl;
        float hy = 1.0f - ly, hx = 1.0f - lx;
        float vf = valid ? 0.25f : 0.0f;
        Samp sp;
        sp.yl = yl; sp.xl = xl; sp.yh = yh; sp.xh = xh;
        sp.w11 = hy * hx * vf; sp.w12 = hy * lx * vf;
        sp.w21 = ly * hx * vf; sp.w22 = ly * lx * vf;
        samp[tid] = sp;
    }
    __syncthreads();

    const float* ft = g_feat_t + ((size_t)b << 24) + tid;
    float* xo = g_x + (size_t)n * ICN;
    __nv_bfloat16* xb = g_xb + (size_t)n * ICN;

    int bstart = half * 25;               // half0: 25 bins, half1: 24 bins
    int pairs = 12;

#pragma unroll 1
    for (int p = 0; p < pairs; p++) {
        int bl = bstart + p * 2;
        float acc0 = 0.0f, acc1 = 0.0f;
#pragma unroll
        for (int s = 0; s < 4; s++) {
            const Samp* sp0 = &samp[bl * 4 + s];
            const Samp* sp1 = &samp[bl * 4 + 4 + s];
            int4 i0 = *(const int4*)(&sp0->yl);
            float4 w0 = *(const float4*)(&sp0->w11);
            int4 i1 = *(const int4*)(&sp1->yl);
            float4 w1_ = *(const float4*)(&sp1->w11);
            float a11 = ft[(i0.x << 16) + (i0.y << 8)];
            float a12 = ft[(i0.x << 16) + (i0.w << 8)];
            float a21 = ft[(i0.z << 16) + (i0.y << 8)];
            float a22 = ft[(i0.z << 16) + (i0.w << 8)];
            float b11 = ft[(i1.x << 16) + (i1.y << 8)];
            float b12 = ft[(i1.x << 16) + (i1.w << 8)];
            float b21 = ft[(i1.z << 16) + (i1.y << 8)];
            float b22 = ft[(i1.z << 16) + (i1.w << 8)];
            acc0 += w0.x * a11 + w0.y * a12 + w0.z * a21 + w0.w * a22;
            acc1 += w1_.x * b11 + w1_.y * b12 + w1_.z * b21 + w1_.w * b22;
        }
        xo[bl * 256 + tid] = acc0;
        xo[(bl + 1) * 256 + tid] = acc1;
        xb[bl * 256 + tid] = __float2bfloat16(acc0);
        xb[(bl + 1) * 256 + tid] = __float2bfloat16(acc1);
    }
    if (half == 0) {   // bin 24
        int bl = 24;
        float acc = 0.0f;
#pragma unroll
        for (int s = 0; s < 4; s++) {
            const Samp* sp = &samp[bl * 4 + s];
            int4 id = *(const int4*)(&sp->yl);
            float4 w = *(const float4*)(&sp->w11);
            acc += w.x * ft[(id.x << 16) + (id.y << 8)]
                 + w.y * ft[(id.x << 16) + (id.w << 8)]
                 + w.z * ft[(id.z << 16) + (id.y << 8)]
                 + w.w * ft[(id.z << 16) + (id.w << 8)];
        }
        xo[bl * 256 + tid] = acc;
        xb[bl * 256 + tid] = __float2bfloat16(acc);
    }
}

// ---------------- kernel 3: GEMM1 split-K partials, bf16 HMMA ----------------
// BM=128, BN=128, BK=64, KSPLIT=4. grid (8,8,4), 256 threads (8 warps 4x2),
// warp tile 32x64. 3-stage cp.async pipeline, 96KB dynamic smem.
#define BM 128
#define BN 128
#define BK 64
#define KT2 (KCH / BK)     // 49
#define STG_A 16384
#define STG_B 16384
#define SB_OFF (3 * STG_A)

__device__ __forceinline__ void ldmatrix_x4(uint32_t* r, uint32_t addr) {
    asm volatile("ldmatrix.sync.aligned.m8n8.x4.shared.b16 {%0,%1,%2,%3}, [%4];"
                 : "=r"(r[0]), "=r"(r[1]), "=r"(r[2]), "=r"(r[3]) : "r"(addr));
}
__device__ __forceinline__ void ldmatrix_x4_trans(uint32_t* r, uint32_t addr) {
    asm volatile("ldmatrix.sync.aligned.m8n8.x4.trans.shared.b16 {%0,%1,%2,%3}, [%4];"
                 : "=r"(r[0]), "=r"(r[1]), "=r"(r[2]), "=r"(r[3]) : "r"(addr));
}

extern __shared__ uint8_t dynsm[];

__global__ void __launch_bounds__(256, 2) gemm1_kernel() {
    uint8_t* sA = dynsm;                 // [3][128 rows][128 B]
    uint8_t* sB = dynsm + SB_OFF;        // [3][64 rows][256 B] (two 128B subrows)

    int t = threadIdx.x;
    int lane = t & 31, warp = t >> 5;
    int wm = warp >> 1, wn = warp & 1;
    int n0 = blockIdx.x * BN;
    int m0 = blockIdx.y * BM;
    int ks = blockIdx.z;

    // ---- A staging: row am (0..127), half ah (0/1), 4 chunks of 16B ----
    int am = t & 127, ah = t >> 7;
    const uint8_t* agp = (const uint8_t*)(g_xb + (size_t)(m0 + am) * ICN + ks * KCH) + ah * 64;
    uint32_t aSm[4];
#pragma unroll
    for (int j = 0; j < 4; j++) {
        int q = ah * 4 + j;
        aSm[j] = smem_u32(sA + am * 128 + ((q ^ (am & 7)) << 4));
    }
    // ---- B staging: row bkr (0..63), 4 chunks (of 16) of 16B ----
    int bkr = t >> 2, bq0 = (t & 3) * 4;
    const uint8_t* bgp = (const uint8_t*)(g_w1b + (size_t)(ks * KCH + bkr) * FC + n0) + bq0 * 16;
    uint32_t bSm[4];
#pragma unroll
    for (int j = 0; j < 4; j++) {
        int q = bq0 + j;
        bSm[j] = smem_u32(sB + bkr * 256 + ((q >> 3) << 7) + (((q & 7) ^ (bkr & 7)) << 4));
    }
    const size_t bStepG = (size_t)BK * FC * 2;   // bytes per k-tile of w1b

    // ---- compute roles ----
    int mRow0 = wm * 32 + (lane & 15);
    int msw = mRow0 & 7;
    int aQsel = lane >> 4;
    uint32_t aBase0 = smem_u32(sA + mRow0 * 128);
    uint32_t aBase1 = aBase0 + 16 * 128;
    int bK = lane & 15;
    uint32_t bBaseRow = smem_u32(sB + bK * 256 + wn * 128);
    int physB[4];
#pragma unroll
    for (int g = 0; g < 4; g++)
        physB[g] = ((g * 2 + (lane >> 4)) ^ (bK & 7)) << 4;

    float acc[2][8][4];
#pragma unroll
    for (int mi = 0; mi < 2; mi++)
#pragma unroll
        for (int ni = 0; ni < 8; ni++)
#pragma unroll
            for (int j = 0; j < 4; j++) acc[mi][ni][j] = 0.0f;

    // prologue: stages 0, 1
#pragma unroll
    for (int s = 0; s < 2; s++) {
        uint32_t ao = s * STG_A, bo = s * STG_B;
        const uint8_t* ag = agp + (size_t)s * 128;
#pragma unroll
        for (int j = 0; j < 4; j++) cp_async16(aSm[j] + ao, ag + j * 16);
        const uint8_t* bg = bgp + (size_t)s * bStepG;
#pragma unroll
        for (int j = 0; j < 4; j++) cp_async16(bSm[j] + bo, bg + j * 16);
        CP_COMMIT();
    }

    int stage = 0;
    for (int kt = 0; kt < KT2; kt++) {
        CP_WAIT(1);
        __syncthreads();

        if (kt + 2 < KT2) {
            int ws = (stage + 2 >= 3) ? stage - 1 : stage + 2;
            uint32_t ao = ws * STG_A, bo = ws * STG_B;
            const uint8_t* ag = agp + (size_t)(kt + 2) * 128;
#pragma unroll
            for (int j = 0; j < 4; j++) cp_async16(aSm[j] + ao, ag + j * 16);
            const uint8_t* bg = bgp + (size_t)(kt + 2) * bStepG;
#pragma unroll
            for (int j = 0; j < 4; j++) cp_async16(bSm[j] + bo, bg + j * 16);
            CP_COMMIT();
        }

        uint32_t ao = stage * STG_A, bo = stage * STG_B;
#pragma unroll
        for (int kk = 0; kk < BK; kk += 16) {
            uint32_t a[2][4], b[4][4];
            int qa = (kk >> 3) + aQsel;
            uint32_t aoff = ao + (uint32_t)((qa ^ msw) << 4);
            ldmatrix_x4(a[0], aBase0 + aoff);
            ldmatrix_x4(a[1], aBase1 + aoff);
            uint32_t boff = bo + (uint32_t)(kk * 256);
#pragma unroll
            for (int g = 0; g < 4; g++)
                ldmatrix_x4_trans(b[g], bBaseRow + boff + physB[g]);
#pragma unroll
            for (int mi = 0; mi < 2; mi++)
#pragma unroll
                for (int ni = 0; ni < 8; ni++) {
                    uint32_t bb0 = b[ni >> 1][(ni & 1) * 2];
                    uint32_t bb1 = b[ni >> 1][(ni & 1) * 2 + 1];
                    asm volatile(
                        "mma.sync.aligned.m16n8k16.row.col.f32.bf16.bf16.f32 "
                        "{%0,%1,%2,%3}, {%4,%5,%6,%7}, {%8,%9}, {%0,%1,%2,%3};"
                        : "+f"(acc[mi][ni][0]), "+f"(acc[mi][ni][1]),
                          "+f"(acc[mi][ni][2]), "+f"(acc[mi][ni][3])
                        : "r"(a[mi][0]), "r"(a[mi][1]), "r"(a[mi][2]), "r"(a[mi][3]),
                          "r"(bb0), "r"(bb1));
                }
        }
        stage = (stage + 1 >= 3) ? 0 : stage + 1;
    }

    // epilogue: write partials
    int tig = lane & 3;
    int gid = lane >> 2;
    float* pbase = g_part[ks];
#pragma unroll
    for (int mi = 0; mi < 2; mi++) {
        int row = m0 + wm * 32 + mi * 16 + gid;
#pragma unroll
        for (int ni = 0; ni < 8; ni++) {
            int col = n0 + wn * 64 + ni * 8 + tig * 2;
            *(float2*)(pbase + (size_t)row * FC + col) =
                make_float2(acc[mi][ni][0], acc[mi][ni][1]);
            *(float2*)(pbase + (size_t)(row + 8) * FC + col) =
                make_float2(acc[mi][ni][2], acc[mi][ni][3]);
        }
    }
}

// ---------------- kernel 3b: reduce partials + bias + relu -------------------
__global__ void __launch_bounds__(256) reduce_kernel(const float* __restrict__ b1) {
    size_t i = (size_t)blockIdx.x * 256 + threadIdx.x;   // float4 index
    int col4 = (int)(i & 255);
    float4 p0 = ((const float4*)g_part[0])[i];
    float4 p1 = ((const float4*)g_part[1])[i];
    float4 p2 = ((const float4*)g_part[2])[i];
    float4 p3 = ((const float4*)g_part[3])[i];
    float4 bb = ((const float4*)b1)[col4];
    float4 o;
    o.x = fmaxf(p0.x + p1.x + p2.x + p3.x + bb.x, 0.0f);
    o.y = fmaxf(p0.y + p1.y + p2.y + p3.y + bb.y, 0.0f);
    o.z = fmaxf(p0.z + p1.z + p2.z + p3.z + bb.z, 0.0f);
    o.w = fmaxf(p0.w + p1.w + p2.w + p3.w + bb.w, 0.0f);
    ((float4*)g_hid)[i] = o;
}

// ---------------- kernel 4: GEMM2 + sigmoid ----------------------------------
__global__ void __launch_bounds__(256) gemm2_kernel(const float* __restrict__ b2) {
    __shared__ float sh[2][FC];
    int n0 = blockIdx.x * 2;
    int tid = threadIdx.x;

    float4* d = (float4*)&sh[0][0];
    const float4* s = (const float4*)(g_hid + (size_t)n0 * FC);
    d[tid] = s[tid];
    d[tid + 256] = s[tid + 256];
    __syncthreads();

    int warp = tid >> 5, lane = tid & 31;
    const float4* h0 = (const float4*)sh[0];
    const float4* h1 = (const float4*)sh[1];
    for (int o = warp; o < NOUT; o += 8) {
        const float4* wr = (const float4*)(g_w2t + (size_t)o * FC);
        float a0 = 0.0f, a1 = 0.0f;
#pragma unroll
        for (int i = 0; i < 8; i++) {
            float4 w = wr[i * 32 + lane];
            float4 x0 = h0[i * 32 + lane];
            float4 x1 = h1[i * 32 + lane];
            a0 += w.x * x0.x + w.y * x0.y + w.z * x0.z + w.w * x0.w;
            a1 += w.x * x1.x + w.y * x1.y + w.z * x1.z + w.w * x1.w;
        }
#pragma unroll
        for (int off = 16; off > 0; off >>= 1) {
            a0 += __shfl_xor_sync(0xffffffffu, a0, off);
            a1 += __shfl_xor_sync(0xffffffffu, a1, off);
        }
        if (lane == 0) {
            float bb = b2[o];
            g_mask[n0 * NOUT + o] = 1.0f / (1.0f + expf(-(a0 + bb)));
            g_mask[(n0 + 1) * NOUT + o] = 1.0f / (1.0f + expf(-(a1 + bb)));
        }
    }
}

// ---------------- kernel 5: out(n,c,hw) = x(n,hw,c) * mask(n,hw) -------------
#define MPAD 261
__global__ void __launch_bounds__(256) modulate_kernel(float* __restrict__ out) {
    __shared__ float sh[25 * MPAD];
    __shared__ float msk[64];
    int n = blockIdx.x;
    int tid = threadIdx.x;
    if (tid < NOUT) msk[tid] = g_mask[n * NOUT + tid];

    const float* xs = g_x + (size_t)n * ICN;
    float* o = out + (size_t)n * ICN;

    for (int i = tid; i < 25 * 256; i += 256) {
        int hw = i >> 8, c = i & 255;
        sh[hw * MPAD + c] = xs[i];
    }
    __syncthreads();
    for (int i = tid; i < 256 * 25; i += 256) {
        int c = i / 25, hw = i - c * 25;
        o[c * 49 + hw] = sh[hw * MPAD + c] * msk[hw];
    }
    __syncthreads();

    for (int i = tid; i < 24 * 256; i += 256) {
        int hw = i >> 8, c = i & 255;
        sh[hw * MPAD + c] = xs[25 * 256 + i];
    }
    __syncthreads();
    for (int i = tid; i < 256 * 24; i += 256) {
        int c = i / 24, hw = i - c * 24;
        o[c * 49 + 25 + hw] = sh[hw * MPAD + c] * msk[25 + hw];
    }
}

// ---------------- launcher ---------------------------------------------------
extern "C" void kernel_launch(void* const* d_in, const int* in_sizes, int n_in,
                              void* d_out, int out_size) {
    const float* features = (const float*)d_in[0];
    const float* rois     = (const float*)d_in[1];
    const float* w1       = (const float*)d_in[2];
    const float* b1       = (const float*)d_in[3];
    const float* w2       = (const float*)d_in[4];
    const float* b2       = (const float*)d_in[5];
    float* out = (float*)d_out;

    cudaFuncSetAttribute(gemm1_kernel,
                         cudaFuncAttributeMaxDynamicSharedMemorySize, 98304);

    transpose_kernel<<<dim3((HH * WW) / 32, CCH / 32, 2), 256>>>(features);
    conv_w1_kernel<<<(ICN * FC / 8) / 256, 256>>>(w1);
    conv_w2_kernel<<<(FC * NOUT + 255) / 256, 256>>>(w2);
    roi_kernel<<<dim3(NROI, 2), 256>>>(rois);
    gemm1_kernel<<<dim3(FC / BN, NROI / BM, KSPLIT), 256, 98304>>>();
    reduce_kernel<<<(NROI * FC / 4) / 256, 256>>>(b1);
    gemm2_kernel<<<NROI / 2, 256>>>(b2);
    modulate_kernel<<<NROI, 256>>>(out);
}

// round 6
// speedup vs baseline: 3.3549x; 1.0675x over previous
#include <cuda_runtime.h>
#include <cuda_fp16.h>
#include <math.h>
#include <stdint.h>

#define HH 256
#define WW 256
#define CCH 256
#define NROI 1024
#define ICN 12544          // 256 * 49
#define FC 1024
#define NOUT 49
#define KSPLIT 4
#define KCH (ICN / KSPLIT)   // 3136

// ---------------- scratch (device globals; no allocations allowed) ----------
__device__ __half g_feat_h[(size_t)2 * 256 * 256 * 256]; // (B,H,W,C) fp16 67MB
__device__ float g_x[(size_t)NROI * ICN];                // (n,HW,C)  51MB fp32
__device__ __half g_xh[(size_t)NROI * ICN];              // fp16 copy (n,HW,C)
__device__ __half g_w1h[(size_t)ICN * FC];               // w1 fp16, K-permuted
__device__ float g_w2t[NOUT * FC];                       // w2 transposed
__device__ float g_part[KSPLIT][(size_t)NROI * FC];      // split-K partials 16MB
__device__ float g_hid[(size_t)NROI * FC];               // 4MB
__device__ float g_mask[NROI * NOUT];

__device__ __forceinline__ uint32_t smem_u32(const void* p) {
    return (uint32_t)__cvta_generic_to_shared(p);
}
__device__ __forceinline__ void cp_async16(uint32_t dst, const void* src) {
    asm volatile("cp.async.cg.shared.global [%0], [%1], 16;\n" :: "r"(dst), "l"(src));
}
#define CP_COMMIT() asm volatile("cp.async.commit_group;\n")
#define CP_WAIT(n)  asm volatile("cp.async.wait_group %0;\n" :: "n"(n))

// ---------------- kernel 1: transpose (B,C,H,W) fp32 -> (B,H,W,C) fp16 -------
__global__ void __launch_bounds__(256) transpose_kernel(const float* __restrict__ f) {
    __shared__ float tile[32][33];
    int b = blockIdx.z;
    int hw0 = blockIdx.x * 32;
    int c0 = blockIdx.y * 32;
    int t = threadIdx.x;

    int ty = t >> 3, tx = t & 7;
    const float* src = f + ((size_t)b * CCH + c0 + ty) * (HH * WW) + hw0 + tx * 4;
    float4 v = *(const float4*)src;
    tile[tx * 4 + 0][ty] = v.x;
    tile[tx * 4 + 1][ty] = v.y;
    tile[tx * 4 + 2][ty] = v.z;
    tile[tx * 4 + 3][ty] = v.w;
    __syncthreads();

    int r = t >> 3, q = t & 7;
    __half2 h0 = __floats2half2_rn(tile[r][q * 4 + 0], tile[r][q * 4 + 1]);
    __half2 h1 = __floats2half2_rn(tile[r][q * 4 + 2], tile[r][q * 4 + 3]);
    uint2 o;
    o.x = *(uint32_t*)&h0;
    o.y = *(uint32_t*)&h1;
    __half* dst = g_feat_h + ((size_t)b << 24) + (size_t)(hw0 + r) * CCH + c0 + q * 4;
    *(uint2*)dst = o;
}

// ---------------- conversions ------------------------------------------------
// w1 fp16 + K-permutation: old row k = c*49+hw  ->  new row k' = hw*256+c
__global__ void __launch_bounds__(256) conv_w1_kernel(const float* __restrict__ w1) {
    size_t i = (size_t)blockIdx.x * 256 + threadIdx.x;
    int row = (int)(i >> 7);
    int col8 = (int)(i & 127);
    int c = row / 49, hw = row - c * 49;
    int nrow = hw * 256 + c;
    const float4* s = (const float4*)(w1 + (size_t)row * FC + col8 * 8);
    float4 a = s[0], bq = s[1];
    __half2 p0 = __floats2half2_rn(a.x, a.y);
    __half2 p1 = __floats2half2_rn(a.z, a.w);
    __half2 p2 = __floats2half2_rn(bq.x, bq.y);
    __half2 p3 = __floats2half2_rn(bq.z, bq.w);
    uint4 out;
    out.x = *(uint32_t*)&p0; out.y = *(uint32_t*)&p1;
    out.z = *(uint32_t*)&p2; out.w = *(uint32_t*)&p3;
    *(uint4*)(g_w1h + (size_t)nrow * FC + col8 * 8) = out;
}

__global__ void conv_w2_kernel(const float* __restrict__ w2) {
    int i = blockIdx.x * 256 + threadIdx.x;
    if (i < FC * NOUT) {
        int k = i / NOUT, o = i - k * NOUT;
        g_w2t[o * FC + k] = w2[i];
    }
}

// ---------------- kernel 2: rotated roi-align (2 blocks per roi) -------------
struct alignas(16) Samp { int yl, xl, yh, xh; float w11, w12, w21, w22; };

__global__ void __launch_bounds__(256, 5) roi_kernel(const float* __restrict__ rois) {
    __shared__ Samp samp[196];
    int n = blockIdx.x;
    int half = blockIdx.y;
    int tid = threadIdx.x;

    const float* r = rois + n * 6;
    int b = (int)r[0];
    float cx = r[1] * 0.125f;
    float cy = r[2] * 0.125f;
    float rw = fmaxf(r[3] * 0.125f, 1.0f);
    float rh = fmaxf(r[4] * 0.125f, 1.0f);
    float theta = r[5];
    float st, ct;
    sincosf(theta, &st, &ct);
    float bw = rw / 7.0f;
    float bh = rh / 7.0f;

    if (tid < 196) {
        int bin = tid >> 2;
        int s = tid & 3;
        int ph = bin / 7, pw = bin - ph * 7;
        int sy = s >> 1, sx = s & 1;
        float yy = -rh * 0.5f + ((float)ph + 0.25f + 0.5f * (float)sy) * bh;
        float xx = -rw * 0.5f + ((float)pw + 0.25f + 0.5f * (float)sx) * bw;
        float xs = xx * ct - yy * st + cx;
        float ys = xx * st + yy * ct + cy;
        bool valid = (ys > -1.0f) && (ys < (float)HH) && (xs > -1.0f) && (xs < (float)WW);
        float ysc = fminf(fmaxf(ys, 0.0f), (float)(HH - 1));
        float xsc = fminf(fmaxf(xs, 0.0f), (float)(WW - 1));
        int yl = (int)floorf(ysc);
        int xl = (int)floorf(xsc);
        int yh = min(yl + 1, HH - 1);
        int xh = min(xl + 1, WW - 1);
        float ly = ysc - (float)yl;
        float lx = xsc - (float)xl;
        float hy = 1.0f - ly, hx = 1.0f - lx;
        float vf = valid ? 0.25f : 0.0f;
        Samp sp;
        sp.yl = yl; sp.xl = xl; sp.yh = yh; sp.xh = xh;
        sp.w11 = hy * hx * vf; sp.w12 = hy * lx * vf;
        sp.w21 = ly * hx * vf; sp.w22 = ly * lx * vf;
        samp[tid] = sp;
    }
    __syncthreads();

    const __half* ft = g_feat_h + ((size_t)b << 24) + tid;
    float* xo = g_x + (size_t)n * ICN;
    __half* xh = g_xh + (size_t)n * ICN;

    int bstart = half * 25;               // half0: 25 bins, half1: 24 bins

#pragma unroll 1
    for (int p = 0; p < 12; p++) {
        int bl = bstart + p * 2;
        float acc0 = 0.0f, acc1 = 0.0f;
#pragma unroll
        for (int s = 0; s < 4; s++) {
            const Samp* sp0 = &samp[bl * 4 + s];
            const Samp* sp1 = &samp[bl * 4 + 4 + s];
            int4 i0 = *(const int4*)(&sp0->yl);
            float4 w0 = *(const float4*)(&sp0->w11);
            int4 i1 = *(const int4*)(&sp1->yl);
            float4 w1_ = *(const float4*)(&sp1->w11);
            float a11 = __half2float(ft[(i0.x << 16) + (i0.y << 8)]);
            float a12 = __half2float(ft[(i0.x << 16) + (i0.w << 8)]);
            float a21 = __half2float(ft[(i0.z << 16) + (i0.y << 8)]);
            float a22 = __half2float(ft[(i0.z << 16) + (i0.w << 8)]);
            float b11 = __half2float(ft[(i1.x << 16) + (i1.y << 8)]);
            float b12 = __half2float(ft[(i1.x << 16) + (i1.w << 8)]);
            float b21 = __half2float(ft[(i1.z << 16) + (i1.y << 8)]);
            float b22 = __half2float(ft[(i1.z << 16) + (i1.w << 8)]);
            acc0 += w0.x * a11 + w0.y * a12 + w0.z * a21 + w0.w * a22;
            acc1 += w1_.x * b11 + w1_.y * b12 + w1_.z * b21 + w1_.w * b22;
        }
        xo[bl * 256 + tid] = acc0;
        xo[(bl + 1) * 256 + tid] = acc1;
        xh[bl * 256 + tid] = __float2half(acc0);
        xh[(bl + 1) * 256 + tid] = __float2half(acc1);
    }
    if (half == 0) {   // bin 24
        int bl = 24;
        float acc = 0.0f;
#pragma unroll
        for (int s = 0; s < 4; s++) {
            const Samp* sp = &samp[bl * 4 + s];
            int4 id = *(const int4*)(&sp->yl);
            float4 w = *(const float4*)(&sp->w11);
            acc += w.x * __half2float(ft[(id.x << 16) + (id.y << 8)])
                 + w.y * __half2float(ft[(id.x << 16) + (id.w << 8)])
                 + w.z * __half2float(ft[(id.z << 16) + (id.y << 8)])
                 + w.w * __half2float(ft[(id.z << 16) + (id.w << 8)]);
        }
        xo[bl * 256 + tid] = acc;
        xh[bl * 256 + tid] = __float2half(acc);
    }
}

// ---------------- kernel 3: GEMM1 split-K partials, fp16 HMMA ----------------
// BM=128, BN=128, BK=64, KSPLIT=4. grid (8,8,4), 256 threads (8 warps 4x2),
// warp tile 32x64. 3-stage cp.async pipeline, 96KB dynamic smem.
#define BM 128
#define BN 128
#define BK 64
#define KT2 (KCH / BK)     // 49
#define STG_A 16384
#define STG_B 16384
#define SB_OFF (3 * STG_A)

__device__ __forceinline__ void ldmatrix_x4(uint32_t* r, uint32_t addr) {
    asm volatile("ldmatrix.sync.aligned.m8n8.x4.shared.b16 {%0,%1,%2,%3}, [%4];"
                 : "=r"(r[0]), "=r"(r[1]), "=r"(r[2]), "=r"(r[3]) : "r"(addr));
}
__device__ __forceinline__ void ldmatrix_x4_trans(uint32_t* r, uint32_t addr) {
    asm volatile("ldmatrix.sync.aligned.m8n8.x4.trans.shared.b16 {%0,%1,%2,%3}, [%4];"
                 : "=r"(r[0]), "=r"(r[1]), "=r"(r[2]), "=r"(r[3]) : "r"(addr));
}

extern __shared__ uint8_t dynsm[];

__global__ void __launch_bounds__(256, 2) gemm1_kernel() {
    uint8_t* sA = dynsm;                 // [3][128 rows][128 B]
    uint8_t* sB = dynsm + SB_OFF;        // [3][64 rows][256 B]

    int t = threadIdx.x;
    int lane = t & 31, warp = t >> 5;
    int wm = warp >> 1, wn = warp & 1;
    int n0 = blockIdx.x * BN;
    int m0 = blockIdx.y * BM;
    int ks = blockIdx.z;

    int am = t & 127, ah = t >> 7;
    const uint8_t* agp = (const uint8_t*)(g_xh + (size_t)(m0 + am) * ICN + ks * KCH) + ah * 64;
    uint32_t aSm[4];
#pragma unroll
    for (int j = 0; j < 4; j++) {
        int q = ah * 4 + j;
        aSm[j] = smem_u32(sA + am * 128 + ((q ^ (am & 7)) << 4));
    }
    int bkr = t >> 2, bq0 = (t & 3) * 4;
    const uint8_t* bgp = (const uint8_t*)(g_w1h + (size_t)(ks * KCH + bkr) * FC + n0) + bq0 * 16;
    uint32_t bSm[4];
#pragma unroll
    for (int j = 0; j < 4; j++) {
        int q = bq0 + j;
        bSm[j] = smem_u32(sB + bkr * 256 + ((q >> 3) << 7) + (((q & 7) ^ (bkr & 7)) << 4));
    }
    const size_t bStepG = (size_t)BK * FC * 2;

    int mRow0 = wm * 32 + (lane & 15);
    int msw = mRow0 & 7;
    int aQsel = lane >> 4;
    uint32_t aBase0 = smem_u32(sA + mRow0 * 128);
    uint32_t aBase1 = aBase0 + 16 * 128;
    int bK = lane & 15;
    uint32_t bBaseRow = smem_u32(sB + bK * 256 + wn * 128);
    int physB[4];
#pragma unroll
    for (int g = 0; g < 4; g++)
        physB[g] = ((g * 2 + (lane >> 4)) ^ (bK & 7)) << 4;

    float acc[2][8][4];
#pragma unroll
    for (int mi = 0; mi < 2; mi++)
#pragma unroll
        for (int ni = 0; ni < 8; ni++)
#pragma unroll
            for (int j = 0; j < 4; j++) acc[mi][ni][j] = 0.0f;

#pragma unroll
    for (int s = 0; s < 2; s++) {
        uint32_t ao = s * STG_A, bo = s * STG_B;
        const uint8_t* ag = agp + (size_t)s * 128;
#pragma unroll
        for (int j = 0; j < 4; j++) cp_async16(aSm[j] + ao, ag + j * 16);
        const uint8_t* bg = bgp + (size_t)s * bStepG;
#pragma unroll
        for (int j = 0; j < 4; j++) cp_async16(bSm[j] + bo, bg + j * 16);
        CP_COMMIT();
    }

    int stage = 0;
    for (int kt = 0; kt < KT2; kt++) {
        CP_WAIT(1);
        __syncthreads();

        if (kt + 2 < KT2) {
            int ws = (stage + 2 >= 3) ? stage - 1 : stage + 2;
            uint32_t ao = ws * STG_A, bo = ws * STG_B;
            const uint8_t* ag = agp + (size_t)(kt + 2) * 128;
#pragma unroll
            for (int j = 0; j < 4; j++) cp_async16(aSm[j] + ao, ag + j * 16);
            const uint8_t* bg = bgp + (size_t)(kt + 2) * bStepG;
#pragma unroll
            for (int j = 0; j < 4; j++) cp_async16(bSm[j] + bo, bg + j * 16);
            CP_COMMIT();
        }

        uint32_t ao = stage * STG_A, bo = stage * STG_B;
#pragma unroll
        for (int kk = 0; kk < BK; kk += 16) {
            uint32_t a[2][4], b[4][4];
            int qa = (kk >> 3) + aQsel;
            uint32_t aoff = ao + (uint32_t)((qa ^ msw) << 4);
            ldmatrix_x4(a[0], aBase0 + aoff);
            ldmatrix_x4(a[1], aBase1 + aoff);
            uint32_t boff = bo + (uint32_t)(kk * 256);
#pragma unroll
            for (int g = 0; g < 4; g++)
                ldmatrix_x4_trans(b[g], bBaseRow + boff + physB[g]);
#pragma unroll
            for (int mi = 0; mi < 2; mi++)
#pragma unroll
                for (int ni = 0; ni < 8; ni++) {
                    uint32_t bb0 = b[ni >> 1][(ni & 1) * 2];
                    uint32_t bb1 = b[ni >> 1][(ni & 1) * 2 + 1];
                    asm volatile(
                        "mma.sync.aligned.m16n8k16.row.col.f32.f16.f16.f32 "
                        "{%0,%1,%2,%3}, {%4,%5,%6,%7}, {%8,%9}, {%0,%1,%2,%3};"
                        : "+f"(acc[mi][ni][0]), "+f"(acc[mi][ni][1]),
                          "+f"(acc[mi][ni][2]), "+f"(acc[mi][ni][3])
                        : "r"(a[mi][0]), "r"(a[mi][1]), "r"(a[mi][2]), "r"(a[mi][3]),
                          "r"(bb0), "r"(bb1));
                }
        }
        stage = (stage + 1 >= 3) ? 0 : stage + 1;
    }

    int tig = lane & 3;
    int gid = lane >> 2;
    float* pbase = g_part[ks];
#pragma unroll
    for (int mi = 0; mi < 2; mi++) {
        int row = m0 + wm * 32 + mi * 16 + gid;
#pragma unroll
        for (int ni = 0; ni < 8; ni++) {
            int col = n0 + wn * 64 + ni * 8 + tig * 2;
            *(float2*)(pbase + (size_t)row * FC + col) =
                make_float2(acc[mi][ni][0], acc[mi][ni][1]);
            *(float2*)(pbase + (size_t)(row + 8) * FC + col) =
                make_float2(acc[mi][ni][2], acc[mi][ni][3]);
        }
    }
}

// ---------------- kernel 3b: reduce partials + bias + relu -------------------
__global__ void __launch_bounds__(256) reduce_kernel(const float* __restrict__ b1) {
    size_t i = (size_t)blockIdx.x * 256 + threadIdx.x;
    int col4 = (int)(i & 255);
    float4 p0 = ((const float4*)g_part[0])[i];
    float4 p1 = ((const float4*)g_part[1])[i];
    float4 p2 = ((const float4*)g_part[2])[i];
    float4 p3 = ((const float4*)g_part[3])[i];
    float4 bb = ((const float4*)b1)[col4];
    float4 o;
    o.x = fmaxf(p0.x + p1.x + p2.x + p3.x + bb.x, 0.0f);
    o.y = fmaxf(p0.y + p1.y + p2.y + p3.y + bb.y, 0.0f);
    o.z = fmaxf(p0.z + p1.z + p2.z + p3.z + bb.z, 0.0f);
    o.w = fmaxf(p0.w + p1.w + p2.w + p3.w + bb.w, 0.0f);
    ((float4*)g_hid)[i] = o;
}

// ---------------- kernel 4: GEMM2 + sigmoid ----------------------------------
__global__ void __launch_bounds__(256) gemm2_kernel(const float* __restrict__ b2) {
    __shared__ float sh[2][FC];
    int n0 = blockIdx.x * 2;
    int tid = threadIdx.x;

    float4* d = (float4*)&sh[0][0];
    const float4* s = (const float4*)(g_hid + (size_t)n0 * FC);
    d[tid] = s[tid];
    d[tid + 256] = s[tid + 256];
    __syncthreads();

    int warp = tid >> 5, lane = tid & 31;
    const float4* h0 = (const float4*)sh[0];
    const float4* h1 = (const float4*)sh[1];
    for (int o = warp; o < NOUT; o += 8) {
        const float4* wr = (const float4*)(g_w2t + (size_t)o * FC);
        float a0 = 0.0f, a1 = 0.0f;
#pragma unroll
        for (int i = 0; i < 8; i++) {
            float4 w = wr[i * 32 + lane];
            float4 x0 = h0[i * 32 + lane];
            float4 x1 = h1[i * 32 + lane];
            a0 += w.x * x0.x + w.y * x0.y + w.z * x0.z + w.w * x0.w;
            a1 += w.x * x1.x + w.y * x1.y + w.z * x1.z + w.w * x1.w;
        }
#pragma unroll
        for (int off = 16; off > 0; off >>= 1) {
            a0 += __shfl_xor_sync(0xffffffffu, a0, off);
            a1 += __shfl_xor_sync(0xffffffffu, a1, off);
        }
        if (lane == 0) {
            float bb = b2[o];
            g_mask[n0 * NOUT + o] = 1.0f / (1.0f + expf(-(a0 + bb)));
            g_mask[(n0 + 1) * NOUT + o] = 1.0f / (1.0f + expf(-(a1 + bb)));
        }
    }
}

// ---------------- kernel 5: out(n,c,hw) = x(n,hw,c) * mask(n,hw) -------------
#define MPAD 261
__global__ void __launch_bounds__(256) modulate_kernel(float* __restrict__ out) {
    __shared__ float sh[25 * MPAD];
    __shared__ float msk[64];
    int n = blockIdx.x;
    int tid = threadIdx.x;
    if (tid < NOUT) msk[tid] = g_mask[n * NOUT + tid];

    const float* xs = g_x + (size_t)n * ICN;
    float* o = out + (size_t)n * ICN;

    for (int i = tid; i < 25 * 256; i += 256) {
        int hw = i >> 8, c = i & 255;
        sh[hw * MPAD + c] = xs[i];
    }
    __syncthreads();
    for (int i = tid; i < 256 * 25; i += 256) {
        int c = i / 25, hw = i - c * 25;
        o[c * 49 + hw] = sh[hw * MPAD + c] * msk[hw];
    }
    __syncthreads();

    for (int i = tid; i < 24 * 256; i += 256) {
        int hw = i >> 8, c = i & 255;
        sh[hw * MPAD + c] = xs[25 * 256 + i];
    }
    __syncthreads();
    for (int i = tid; i < 256 * 24; i += 256) {
        int c = i / 24, hw = i - c * 24;
        o[c * 49 + 25 + hw] = sh[hw * MPAD + c] * msk[25 + hw];
    }
}

// ---------------- launcher ---------------------------------------------------
extern "C" void kernel_launch(void* const* d_in, const int* in_sizes, int n_in,
                              void* d_out, int out_size) {
    const float* features = (const float*)d_in[0];
    const float* rois     = (const float*)d_in[1];
    const float* w1       = (const float*)d_in[2];
    const float* b1       = (const float*)d_in[3];
    const float* w2       = (const float*)d_in[4];
    const float* b2       = (const float*)d_in[5];
    float* out = (float*)d_out;

    cudaFuncSetAttribute(gemm1_kernel,
                         cudaFuncAttributeMaxDynamicSharedMemorySize, 98304);

    transpose_kernel<<<dim3((HH * WW) / 32, CCH / 32, 2), 256>>>(features);
    conv_w1_kernel<<<(ICN * FC / 8) / 256, 256>>>(w1);
    conv_w2_kernel<<<(FC * NOUT + 255) / 256, 256>>>(w2);
    roi_kernel<<<dim3(NROI, 2), 256>>>(rois);
    gemm1_kernel<<<dim3(FC / BN, NROI / BM, KSPLIT), 256, 98304>>>();
    reduce_kernel<<<(NROI * FC / 4) / 256, 256>>>(b1);
    gemm2_kernel<<<NROI / 2, 256>>>(b2);
    modulate_kernel<<<NROI, 256>>>(out);
}

// round 7
// speedup vs baseline: 3.7031x; 1.1038x over previous
#include <cuda_runtime.h>
#include <cuda_fp16.h>
#include <math.h>
#include <stdint.h>

#define HH 256
#define WW 256
#define CCH 256
#define NROI 1024
#define ICN 12544          // 256 * 49
#define FC 1024
#define NOUT 49
#define KSPLIT 4
#define KCH (ICN / KSPLIT)   // 3136

// ---------------- scratch (device globals; no allocations allowed) ----------
__device__ __half g_feat_h[(size_t)2 * 256 * 256 * 256]; // (B,H,W,C) fp16 67MB
__device__ float g_x[(size_t)NROI * ICN];                // (n,HW,C)  51MB fp32
__device__ __half g_xh[(size_t)NROI * ICN];              // fp16 copy (n,HW,C)
__device__ __half g_w1h[(size_t)ICN * FC];               // w1 fp16, K-permuted
__device__ float g_w2t[NOUT * FC];                       // w2 transposed
__device__ float g_part[KSPLIT][(size_t)NROI * FC];      // split-K partials 16MB
__device__ float g_hid[(size_t)NROI * FC];               // 4MB
__device__ float g_mask[NROI * NOUT];

__device__ __forceinline__ uint32_t smem_u32(const void* p) {
    return (uint32_t)__cvta_generic_to_shared(p);
}
__device__ __forceinline__ void cp_async16(uint32_t dst, const void* src) {
    asm volatile("cp.async.cg.shared.global [%0], [%1], 16;\n" :: "r"(dst), "l"(src));
}
#define CP_COMMIT() asm volatile("cp.async.commit_group;\n")
#define CP_WAIT(n)  asm volatile("cp.async.wait_group %0;\n" :: "n"(n))

// ---------------- kernel 1: transpose (B,C,H,W) fp32 -> (B,H,W,C) fp16 -------
__global__ void __launch_bounds__(256) transpose_kernel(const float* __restrict__ f) {
    __shared__ float tile[32][33];
    int b = blockIdx.z;
    int hw0 = blockIdx.x * 32;
    int c0 = blockIdx.y * 32;
    int t = threadIdx.x;

    int ty = t >> 3, tx = t & 7;
    const float* src = f + ((size_t)b * CCH + c0 + ty) * (HH * WW) + hw0 + tx * 4;
    float4 v = *(const float4*)src;
    tile[tx * 4 + 0][ty] = v.x;
    tile[tx * 4 + 1][ty] = v.y;
    tile[tx * 4 + 2][ty] = v.z;
    tile[tx * 4 + 3][ty] = v.w;
    __syncthreads();

    int r = t >> 3, q = t & 7;
    __half2 h0 = __floats2half2_rn(tile[r][q * 4 + 0], tile[r][q * 4 + 1]);
    __half2 h1 = __floats2half2_rn(tile[r][q * 4 + 2], tile[r][q * 4 + 3]);
    uint2 o;
    o.x = *(uint32_t*)&h0;
    o.y = *(uint32_t*)&h1;
    __half* dst = g_feat_h + ((size_t)b << 24) + (size_t)(hw0 + r) * CCH + c0 + q * 4;
    *(uint2*)dst = o;
}

// ---------------- conversions ------------------------------------------------
// w1 fp16 + K-permutation: old row k = c*49+hw  ->  new row k' = hw*256+c
__global__ void __launch_bounds__(256) conv_w1_kernel(const float* __restrict__ w1) {
    size_t i = (size_t)blockIdx.x * 256 + threadIdx.x;
    int row = (int)(i >> 7);
    int col8 = (int)(i & 127);
    int c = row / 49, hw = row - c * 49;
    int nrow = hw * 256 + c;
    const float4* s = (const float4*)(w1 + (size_t)row * FC + col8 * 8);
    float4 a = s[0], bq = s[1];
    __half2 p0 = __floats2half2_rn(a.x, a.y);
    __half2 p1 = __floats2half2_rn(a.z, a.w);
    __half2 p2 = __floats2half2_rn(bq.x, bq.y);
    __half2 p3 = __floats2half2_rn(bq.z, bq.w);
    uint4 out;
    out.x = *(uint32_t*)&p0; out.y = *(uint32_t*)&p1;
    out.z = *(uint32_t*)&p2; out.w = *(uint32_t*)&p3;
    *(uint4*)(g_w1h + (size_t)nrow * FC + col8 * 8) = out;
}

__global__ void conv_w2_kernel(const float* __restrict__ w2) {
    int i = blockIdx.x * 256 + threadIdx.x;
    if (i < FC * NOUT) {
        int k = i / NOUT, o = i - k * NOUT;
        g_w2t[o * FC + k] = w2[i];
    }
}

// ---------------- kernel 2: rotated roi-align (2 blocks/roi, half2 lanes) ----
struct alignas(16) Samp { int yl, xl, yh, xh; float w11, w12, w21, w22; };

__device__ __forceinline__ void roi_bin(const __half2* __restrict__ ft2,
                                        const Samp* __restrict__ samp,
                                        int bl, float2& acc) {
    acc.x = 0.0f; acc.y = 0.0f;
#pragma unroll
    for (int s = 0; s < 4; s++) {
        const Samp* sp = &samp[bl * 4 + s];
        int4 id = *(const int4*)(&sp->yl);
        float4 w = *(const float4*)(&sp->w11);
        __half2 v11 = ft2[(id.x << 15) + (id.y << 7)];
        __half2 v12 = ft2[(id.x << 15) + (id.w << 7)];
        __half2 v21 = ft2[(id.z << 15) + (id.y << 7)];
        __half2 v22 = ft2[(id.z << 15) + (id.w << 7)];
        float2 f11 = __half22float2(v11);
        float2 f12 = __half22float2(v12);
        float2 f21 = __half22float2(v21);
        float2 f22 = __half22float2(v22);
        acc.x += w.x * f11.x + w.y * f12.x + w.z * f21.x + w.w * f22.x;
        acc.y += w.x * f11.y + w.y * f12.y + w.z * f21.y + w.w * f22.y;
    }
}

__global__ void __launch_bounds__(256, 5) roi_kernel(const float* __restrict__ rois) {
    __shared__ Samp samp[196];
    int n = blockIdx.x;
    int half = blockIdx.y;
    int tid = threadIdx.x;

    const float* r = rois + n * 6;
    int b = (int)r[0];
    float cx = r[1] * 0.125f;
    float cy = r[2] * 0.125f;
    float rw = fmaxf(r[3] * 0.125f, 1.0f);
    float rh = fmaxf(r[4] * 0.125f, 1.0f);
    float theta = r[5];
    float st, ct;
    sincosf(theta, &st, &ct);
    float bw = rw / 7.0f;
    float bh = rh / 7.0f;

    if (tid < 196) {
        int bin = tid >> 2;
        int s = tid & 3;
        int ph = bin / 7, pw = bin - ph * 7;
        int sy = s >> 1, sx = s & 1;
        float yy = -rh * 0.5f + ((float)ph + 0.25f + 0.5f * (float)sy) * bh;
        float xx = -rw * 0.5f + ((float)pw + 0.25f + 0.5f * (float)sx) * bw;
        float xs = xx * ct - yy * st + cx;
        float ys = xx * st + yy * ct + cy;
        bool valid = (ys > -1.0f) && (ys < (float)HH) && (xs > -1.0f) && (xs < (float)WW);
        float ysc = fminf(fmaxf(ys, 0.0f), (float)(HH - 1));
        float xsc = fminf(fmaxf(xs, 0.0f), (float)(WW - 1));
        int yl = (int)floorf(ysc);
        int xl = (int)floorf(xsc);
        int yh = min(yl + 1, HH - 1);
        int xh = min(xl + 1, WW - 1);
        float ly = ysc - (float)yl;
        float lx = xsc - (float)xl;
        float hy = 1.0f - ly, hx = 1.0f - lx;
        float vf = valid ? 0.25f : 0.0f;
        Samp sp;
        sp.yl = yl; sp.xl = xl; sp.yh = yh; sp.xh = xh;
        sp.w11 = hy * hx * vf; sp.w12 = hy * lx * vf;
        sp.w21 = ly * hx * vf; sp.w22 = ly * lx * vf;
        samp[tid] = sp;
    }
    __syncthreads();

    int c2 = tid & 127;        // channel-pair index: channels 2c2, 2c2+1
    int sub = tid >> 7;        // bin interleave
    const __half2* ft2 = (const __half2*)(g_feat_h + ((size_t)b << 24)) + c2;
    float* xo = g_x + (size_t)n * ICN + 2 * c2;
    __half* xh = g_xh + (size_t)n * ICN + 2 * c2;

    int bstart = half * 25;
    int bend = bstart + (half ? 24 : 25);

    int bl = bstart + sub;
#pragma unroll 1
    for (; bl + 2 < bend; bl += 4) {
        float2 a0, a1;
        roi_bin(ft2, samp, bl, a0);
        roi_bin(ft2, samp, bl + 2, a1);
        *(float2*)(xo + bl * 256) = a0;
        *(float2*)(xo + (bl + 2) * 256) = a1;
        *(__half2*)(xh + bl * 256) = __floats2half2_rn(a0.x, a0.y);
        *(__half2*)(xh + (bl + 2) * 256) = __floats2half2_rn(a1.x, a1.y);
    }
    if (bl < bend) {
        float2 a0;
        roi_bin(ft2, samp, bl, a0);
        *(float2*)(xo + bl * 256) = a0;
        *(__half2*)(xh + bl * 256) = __floats2half2_rn(a0.x, a0.y);
    }
}

// ---------------- kernel 3: GEMM1 split-K partials, fp16 HMMA ----------------
// BM=128, BN=128, BK=64, KSPLIT=4. grid (8,8,4), 256 threads (8 warps 4x2),
// warp tile 32x64. 3-stage cp.async pipeline, 96KB dynamic smem.
#define BM 128
#define BN 128
#define BK 64
#define KT2 (KCH / BK)     // 49
#define STG_A 16384
#define STG_B 16384
#define SB_OFF (3 * STG_A)

__device__ __forceinline__ void ldmatrix_x4(uint32_t* r, uint32_t addr) {
    asm volatile("ldmatrix.sync.aligned.m8n8.x4.shared.b16 {%0,%1,%2,%3}, [%4];"
                 : "=r"(r[0]), "=r"(r[1]), "=r"(r[2]), "=r"(r[3]) : "r"(addr));
}
__device__ __forceinline__ void ldmatrix_x4_trans(uint32_t* r, uint32_t addr) {
    asm volatile("ldmatrix.sync.aligned.m8n8.x4.trans.shared.b16 {%0,%1,%2,%3}, [%4];"
                 : "=r"(r[0]), "=r"(r[1]), "=r"(r[2]), "=r"(r[3]) : "r"(addr));
}

extern __shared__ uint8_t dynsm[];

__global__ void __launch_bounds__(256, 2) gemm1_kernel() {
    uint8_t* sA = dynsm;                 // [3][128 rows][128 B]
    uint8_t* sB = dynsm + SB_OFF;        // [3][64 rows][256 B]

    int t = threadIdx.x;
    int lane = t & 31, warp = t >> 5;
    int wm = warp >> 1, wn = warp & 1;
    int n0 = blockIdx.x * BN;
    int m0 = blockIdx.y * BM;
    int ks = blockIdx.z;

    int am = t & 127, ah = t >> 7;
    const uint8_t* agp = (const uint8_t*)(g_xh + (size_t)(m0 + am) * ICN + ks * KCH) + ah * 64;
    uint32_t aSm[4];
#pragma unroll
    for (int j = 0; j < 4; j++) {
        int q = ah * 4 + j;
        aSm[j] = smem_u32(sA + am * 128 + ((q ^ (am & 7)) << 4));
    }
    int bkr = t >> 2, bq0 = (t & 3) * 4;
    const uint8_t* bgp = (const uint8_t*)(g_w1h + (size_t)(ks * KCH + bkr) * FC + n0) + bq0 * 16;
    uint32_t bSm[4];
#pragma unroll
    for (int j = 0; j < 4; j++) {
        int q = bq0 + j;
        bSm[j] = smem_u32(sB + bkr * 256 + ((q >> 3) << 7) + (((q & 7) ^ (bkr & 7)) << 4));
    }
    const size_t bStepG = (size_t)BK * FC * 2;

    int mRow0 = wm * 32 + (lane & 15);
    int msw = mRow0 & 7;
    int aQsel = lane >> 4;
    uint32_t aBase0 = smem_u32(sA + mRow0 * 128);
    uint32_t aBase1 = aBase0 + 16 * 128;
    int bK = lane & 15;
    uint32_t bBaseRow = smem_u32(sB + bK * 256 + wn * 128);
    int physB[4];
#pragma unroll
    for (int g = 0; g < 4; g++)
        physB[g] = ((g * 2 + (lane >> 4)) ^ (bK & 7)) << 4;

    float acc[2][8][4];
#pragma unroll
    for (int mi = 0; mi < 2; mi++)
#pragma unroll
        for (int ni = 0; ni < 8; ni++)
#pragma unroll
            for (int j = 0; j < 4; j++) acc[mi][ni][j] = 0.0f;

#pragma unroll
    for (int s = 0; s < 2; s++) {
        uint32_t ao = s * STG_A, bo = s * STG_B;
        const uint8_t* ag = agp + (size_t)s * 128;
#pragma unroll
        for (int j = 0; j < 4; j++) cp_async16(aSm[j] + ao, ag + j * 16);
        const uint8_t* bg = bgp + (size_t)s * bStepG;
#pragma unroll
        for (int j = 0; j < 4; j++) cp_async16(bSm[j] + bo, bg + j * 16);
        CP_COMMIT();
    }

    int stage = 0;
    for (int kt = 0; kt < KT2; kt++) {
        CP_WAIT(1);
        __syncthreads();

        if (kt + 2 < KT2) {
            int ws = (stage + 2 >= 3) ? stage - 1 : stage + 2;
            uint32_t ao = ws * STG_A, bo = ws * STG_B;
            const uint8_t* ag = agp + (size_t)(kt + 2) * 128;
#pragma unroll
            for (int j = 0; j < 4; j++) cp_async16(aSm[j] + ao, ag + j * 16);
            const uint8_t* bg = bgp + (size_t)(kt + 2) * bStepG;
#pragma unroll
            for (int j = 0; j < 4; j++) cp_async16(bSm[j] + bo, bg + j * 16);
            CP_COMMIT();
        }

        uint32_t ao = stage * STG_A, bo = stage * STG_B;
#pragma unroll
        for (int kk = 0; kk < BK; kk += 16) {
            uint32_t a[2][4], b[4][4];
            int qa = (kk >> 3) + aQsel;
            uint32_t aoff = ao + (uint32_t)((qa ^ msw) << 4);
            ldmatrix_x4(a[0], aBase0 + aoff);
            ldmatrix_x4(a[1], aBase1 + aoff);
            uint32_t boff = bo + (uint32_t)(kk * 256);
#pragma unroll
            for (int g = 0; g < 4; g++)
                ldmatrix_x4_trans(b[g], bBaseRow + boff + physB[g]);
#pragma unroll
            for (int mi = 0; mi < 2; mi++)
#pragma unroll
                for (int ni = 0; ni < 8; ni++) {
                    uint32_t bb0 = b[ni >> 1][(ni & 1) * 2];
                    uint32_t bb1 = b[ni >> 1][(ni & 1) * 2 + 1];
                    asm volatile(
                        "mma.sync.aligned.m16n8k16.row.col.f32.f16.f16.f32 "
                        "{%0,%1,%2,%3}, {%4,%5,%6,%7}, {%8,%9}, {%0,%1,%2,%3};"
                        : "+f"(acc[mi][ni][0]), "+f"(acc[mi][ni][1]),
                          "+f"(acc[mi][ni][2]), "+f"(acc[mi][ni][3])
                        : "r"(a[mi][0]), "r"(a[mi][1]), "r"(a[mi][2]), "r"(a[mi][3]),
                          "r"(bb0), "r"(bb1));
                }
        }
        stage = (stage + 1 >= 3) ? 0 : stage + 1;
    }

    int tig = lane & 3;
    int gid = lane >> 2;
    float* pbase = g_part[ks];
#pragma unroll
    for (int mi = 0; mi < 2; mi++) {
        int row = m0 + wm * 32 + mi * 16 + gid;
#pragma unroll
        for (int ni = 0; ni < 8; ni++) {
            int col = n0 + wn * 64 + ni * 8 + tig * 2;
            *(float2*)(pbase + (size_t)row * FC + col) =
                make_float2(acc[mi][ni][0], acc[mi][ni][1]);
            *(float2*)(pbase + (size_t)(row + 8) * FC + col) =
                make_float2(acc[mi][ni][2], acc[mi][ni][3]);
        }
    }
}

// ---------------- kernel 3b: reduce partials + bias + relu -------------------
__global__ void __launch_bounds__(256) reduce_kernel(const float* __restrict__ b1) {
    size_t i = (size_t)blockIdx.x * 256 + threadIdx.x;
    int col4 = (int)(i & 255);
    float4 p0 = ((const float4*)g_part[0])[i];
    float4 p1 = ((const float4*)g_part[1])[i];
    float4 p2 = ((const float4*)g_part[2])[i];
    float4 p3 = ((const float4*)g_part[3])[i];
    float4 bb = ((const float4*)b1)[col4];
    float4 o;
    o.x = fmaxf(p0.x + p1.x + p2.x + p3.x + bb.x, 0.0f);
    o.y = fmaxf(p0.y + p1.y + p2.y + p3.y + bb.y, 0.0f);
    o.z = fmaxf(p0.z + p1.z + p2.z + p3.z + bb.z, 0.0f);
    o.w = fmaxf(p0.w + p1.w + p2.w + p3.w + bb.w, 0.0f);
    ((float4*)g_hid)[i] = o;
}

// ---------------- kernel 4: GEMM2 + sigmoid ----------------------------------
__global__ void __launch_bounds__(256) gemm2_kernel(const float* __restrict__ b2) {
    __shared__ float sh[2][FC];
    int n0 = blockIdx.x * 2;
    int tid = threadIdx.x;

    float4* d = (float4*)&sh[0][0];
    const float4* s = (const float4*)(g_hid + (size_t)n0 * FC);
    d[tid] = s[tid];
    d[tid + 256] = s[tid + 256];
    __syncthreads();

    int warp = tid >> 5, lane = tid & 31;
    const float4* h0 = (const float4*)sh[0];
    const float4* h1 = (const float4*)sh[1];
    for (int o = warp; o < NOUT; o += 8) {
        const float4* wr = (const float4*)(g_w2t + (size_t)o * FC);
        float a0 = 0.0f, a1 = 0.0f;
#pragma unroll
        for (int i = 0; i < 8; i++) {
            float4 w = wr[i * 32 + lane];
            float4 x0 = h0[i * 32 + lane];
            float4 x1 = h1[i * 32 + lane];
            a0 += w.x * x0.x + w.y * x0.y + w.z * x0.z + w.w * x0.w;
            a1 += w.x * x1.x + w.y * x1.y + w.z * x1.z + w.w * x1.w;
        }
#pragma unroll
        for (int off = 16; off > 0; off >>= 1) {
            a0 += __shfl_xor_sync(0xffffffffu, a0, off);
            a1 += __shfl_xor_sync(0xffffffffu, a1, off);
        }
        if (lane == 0) {
            float bb = b2[o];
            g_mask[n0 * NOUT + o] = 1.0f / (1.0f + expf(-(a0 + bb)));
            g_mask[(n0 + 1) * NOUT + o] = 1.0f / (1.0f + expf(-(a1 + bb)));
        }
    }
}

// ---------------- kernel 5: out(n,c,hw) = x(n,hw,c) * mask(n,hw) -------------
#define MPAD 261
__global__ void __launch_bounds__(256) modulate_kernel(float* __restrict__ out) {
    __shared__ float sh[25 * MPAD];
    __shared__ float msk[64];
    int n = blockIdx.x;
    int tid = threadIdx.x;
    if (tid < NOUT) msk[tid] = g_mask[n * NOUT + tid];

    const float* xs = g_x + (size_t)n * ICN;
    float* o = out + (size_t)n * ICN;

    for (int i = tid; i < 25 * 256; i += 256) {
        int hw = i >> 8, c = i & 255;
        sh[hw * MPAD + c] = xs[i];
    }
    __syncthreads();
    for (int i = tid; i < 256 * 25; i += 256) {
        int c = i / 25, hw = i - c * 25;
        o[c * 49 + hw] = sh[hw * MPAD + c] * msk[hw];
    }
    __syncthreads();

    for (int i = tid; i < 24 * 256; i += 256) {
        int hw = i >> 8, c = i & 255;
        sh[hw * MPAD + c] = xs[25 * 256 + i];
    }
    __syncthreads();
    for (int i = tid; i < 256 * 24; i += 256) {
        int c = i / 24, hw = i - c * 24;
        o[c * 49 + 25 + hw] = sh[hw * MPAD + c] * msk[25 + hw];
    }
}

// ---------------- launcher ---------------------------------------------------
extern "C" void kernel_launch(void* const* d_in, const int* in_sizes, int n_in,
                              void* d_out, int out_size) {
    const float* features = (const float*)d_in[0];
    const float* rois     = (const float*)d_in[1];
    const float* w1       = (const float*)d_in[2];
    const float* b1       = (const float*)d_in[3];
    const float* w2       = (const float*)d_in[4];
    const float* b2       = (const float*)d_in[5];
    float* out = (float*)d_out;

    cudaFuncSetAttribute(gemm1_kernel,
                         cudaFuncAttributeMaxDynamicSharedMemorySize, 98304);

    transpose_kernel<<<dim3((HH * WW) / 32, CCH / 32, 2), 256>>>(features);
    conv_w1_kernel<<<(ICN * FC / 8) / 256, 256>>>(w1);
    conv_w2_kernel<<<(FC * NOUT + 255) / 256, 256>>>(w2);
    roi_kernel<<<dim3(NROI, 2), 256>>>(rois);
    gemm1_kernel<<<dim3(FC / BN, NROI / BM, KSPLIT), 256, 98304>>>();
    reduce_kernel<<<(NROI * FC / 4) / 256, 256>>>(b1);
    gemm2_kernel<<<NROI / 2, 256>>>(b2);
    modulate_kernel<<<NROI, 256>>>(out);
}

// round 9
// speedup vs baseline: 3.7128x; 1.0026x over previous
#include <cuda_runtime.h>
#include <cuda_fp16.h>
#include <math.h>
#include <stdint.h>

#define HH 256
#define WW 256
#define CCH 256
#define NROI 1024
#define ICN 12544          // 256 * 49
#define FC 1024
#define NOUT 49
#define KSPLIT 4
#define KCH (ICN / KSPLIT)   // 3136

// ---------------- scratch (device globals; no allocations allowed) ----------
__device__ __align__(16) __half g_feat_h[(size_t)2 * 256 * 256 * 256]; // (B,H,W,C) fp16
__device__ __align__(16) __half g_xh[(size_t)NROI * ICN];    // x fp16 (n,HW,C)
__device__ __align__(16) __half g_w1h[(size_t)ICN * FC];     // w1 fp16, K-permuted
__device__ float g_w2t[NOUT * FC];                           // w2 transposed
__device__ float g_part[KSPLIT][(size_t)NROI * FC];          // split-K partials
__device__ float g_hid[(size_t)NROI * FC];
__device__ float g_mask[NROI * NOUT];

__device__ __forceinline__ uint32_t smem_u32(const void* p) {
    return (uint32_t)__cvta_generic_to_shared(p);
}
__device__ __forceinline__ void cp_async16(uint32_t dst, const void* src) {
    asm volatile("cp.async.cg.shared.global [%0], [%1], 16;\n" :: "r"(dst), "l"(src));
}
#define CP_COMMIT() asm volatile("cp.async.commit_group;\n")
#define CP_WAIT(n)  asm volatile("cp.async.wait_group %0;\n" :: "n"(n))

// ---------------- kernel 1: transpose (B,C,H,W) fp32 -> (B,H,W,C) fp16 -------
__global__ void __launch_bounds__(256) transpose_kernel(const float* __restrict__ f) {
    __shared__ float tile[32][33];
    int b = blockIdx.z;
    int hw0 = blockIdx.x * 32;
    int c0 = blockIdx.y * 32;
    int t = threadIdx.x;

    int ty = t >> 3, tx = t & 7;
    const float* src = f + ((size_t)b * CCH + c0 + ty) * (HH * WW) + hw0 + tx * 4;
    float4 v = *(const float4*)src;
    tile[tx * 4 + 0][ty] = v.x;
    tile[tx * 4 + 1][ty] = v.y;
    tile[tx * 4 + 2][ty] = v.z;
    tile[tx * 4 + 3][ty] = v.w;
    __syncthreads();

    int r = t >> 3, q = t & 7;
    __half2 h0 = __floats2half2_rn(tile[r][q * 4 + 0], tile[r][q * 4 + 1]);
    __half2 h1 = __floats2half2_rn(tile[r][q * 4 + 2], tile[r][q * 4 + 3]);
    uint2 o;
    o.x = *(uint32_t*)&h0;
    o.y = *(uint32_t*)&h1;
    __half* dst = g_feat_h + ((size_t)b << 24) + (size_t)(hw0 + r) * CCH + c0 + q * 4;
    *(uint2*)dst = o;
}

// ---------------- conversions ------------------------------------------------
// w1 fp16 + K-permutation: old row k = c*49+hw  ->  new row k' = hw*256+c
__global__ void __launch_bounds__(256) conv_w1_kernel(const float* __restrict__ w1) {
    size_t i = (size_t)blockIdx.x * 256 + threadIdx.x;
    int row = (int)(i >> 7);
    int col8 = (int)(i & 127);
    int c = row / 49, hw = row - c * 49;
    int nrow = hw * 256 + c;
    const float4* s = (const float4*)(w1 + (size_t)row * FC + col8 * 8);
    float4 a = s[0], bq = s[1];
    __half2 p0 = __floats2half2_rn(a.x, a.y);
    __half2 p1 = __floats2half2_rn(a.z, a.w);
    __half2 p2 = __floats2half2_rn(bq.x, bq.y);
    __half2 p3 = __floats2half2_rn(bq.z, bq.w);
    uint4 out;
    out.x = *(uint32_t*)&p0; out.y = *(uint32_t*)&p1;
    out.z = *(uint32_t*)&p2; out.w = *(uint32_t*)&p3;
    *(uint4*)(g_w1h + (size_t)nrow * FC + col8 * 8) = out;
}

__global__ void conv_w2_kernel(const float* __restrict__ w2) {
    int i = blockIdx.x * 256 + threadIdx.x;
    if (i < FC * NOUT) {
        int k = i / NOUT, o = i - k * NOUT;
        g_w2t[o * FC + k] = w2[i];
    }
}

// ---------------- kernel 2: rotated roi-align (2 blocks/roi, half2 lanes) ----
struct alignas(16) Samp { int yl, xl, yh, xh; float w11, w12, w21, w22; };

__device__ __forceinline__ void roi_bin(const __half2* __restrict__ ft2,
                                        const Samp* __restrict__ samp,
                                        int bl, float2& acc) {
    acc.x = 0.0f; acc.y = 0.0f;
#pragma unroll
    for (int s = 0; s < 4; s++) {
        const Samp* sp = &samp[bl * 4 + s];
        int4 id = *(const int4*)(&sp->yl);
        float4 w = *(const float4*)(&sp->w11);
        __half2 v11 = ft2[(id.x << 15) + (id.y << 7)];
        __half2 v12 = ft2[(id.x << 15) + (id.w << 7)];
        __half2 v21 = ft2[(id.z << 15) + (id.y << 7)];
        __half2 v22 = ft2[(id.z << 15) + (id.w << 7)];
        float2 f11 = __half22float2(v11);
        float2 f12 = __half22float2(v12);
        float2 f21 = __half22float2(v21);
        float2 f22 = __half22float2(v22);
        acc.x += w.x * f11.x + w.y * f12.x + w.z * f21.x + w.w * f22.x;
        acc.y += w.x * f11.y + w.y * f12.y + w.z * f21.y + w.w * f22.y;
    }
}

__global__ void __launch_bounds__(256, 5) roi_kernel(const float* __restrict__ rois) {
    __shared__ Samp samp[196];
    int n = blockIdx.x;
    int half = blockIdx.y;
    int tid = threadIdx.x;

    const float* r = rois + n * 6;
    int b = (int)r[0];
    float cx = r[1] * 0.125f;
    float cy = r[2] * 0.125f;
    float rw = fmaxf(r[3] * 0.125f, 1.0f);
    float rh = fmaxf(r[4] * 0.125f, 1.0f);
    float theta = r[5];
    float st, ct;
    sincosf(theta, &st, &ct);
    float bw = rw / 7.0f;
    float bh = rh / 7.0f;

    if (tid < 196) {
        int bin = tid >> 2;
        int s = tid & 3;
        int ph = bin / 7, pw = bin - ph * 7;
        int sy = s >> 1, sx = s & 1;
        float yy = -rh * 0.5f + ((float)ph + 0.25f + 0.5f * (float)sy) * bh;
        float xx = -rw * 0.5f + ((float)pw + 0.25f + 0.5f * (float)sx) * bw;
        float xs = xx * ct - yy * st + cx;
        float ys = xx * st + yy * ct + cy;
        bool valid = (ys > -1.0f) && (ys < (float)HH) && (xs > -1.0f) && (xs < (float)WW);
        float ysc = fminf(fmaxf(ys, 0.0f), (float)(HH - 1));
        float xsc = fminf(fmaxf(xs, 0.0f), (float)(WW - 1));
        int yl = (int)floorf(ysc);
        int xl = (int)floorf(xsc);
        int yh = min(yl + 1, HH - 1);
        int xh = min(xl + 1, WW - 1);
        float ly = ysc - (float)yl;
        float lx = xsc - (float)xl;
        float hy = 1.0f - ly, hx = 1.0f - lx;
        float vf = valid ? 0.25f : 0.0f;
        Samp sp;
        sp.yl = yl; sp.xl = xl; sp.yh = yh; sp.xh = xh;
        sp.w11 = hy * hx * vf; sp.w12 = hy * lx * vf;
        sp.w21 = ly * hx * vf; sp.w22 = ly * lx * vf;
        samp[tid] = sp;
    }
    __syncthreads();

    int c2 = tid & 127;        // channel-pair index: channels 2c2, 2c2+1
    int sub = tid >> 7;        // bin interleave
    const __half2* ft2 = (const __half2*)(g_feat_h + ((size_t)b << 24)) + c2;
    __half* xh = g_xh + (size_t)n * ICN + 2 * c2;

    int bstart = half * 25;
    int bend = bstart + (half ? 24 : 25);

    int bl = bstart + sub;
#pragma unroll 1
    for (; bl + 2 < bend; bl += 4) {
        float2 a0, a1;
        roi_bin(ft2, samp, bl, a0);
        roi_bin(ft2, samp, bl + 2, a1);
        *(__half2*)(xh + bl * 256) = __floats2half2_rn(a0.x, a0.y);
        *(__half2*)(xh + (bl + 2) * 256) = __floats2half2_rn(a1.x, a1.y);
    }
    if (bl < bend) {
        float2 a0;
        roi_bin(ft2, samp, bl, a0);
        *(__half2*)(xh + bl * 256) = __floats2half2_rn(a0.x, a0.y);
    }
}

// ---------------- kernel 3: GEMM1 split-K partials, fp16 HMMA ----------------
// BM=128, BN=128, BK=64, KSPLIT=4. grid (8,8,4), 256 threads (8 warps 4x2),
// warp tile 32x64. 3-stage cp.async pipeline, 96KB dynamic smem.
#define BM 128
#define BN 128
#define BK 64
#define KT2 (KCH / BK)     // 49
#define STG_A 16384
#define STG_B 16384
#define SB_OFF (3 * STG_A)

__device__ __forceinline__ void ldmatrix_x4(uint32_t* r, uint32_t addr) {
    asm volatile("ldmatrix.sync.aligned.m8n8.x4.shared.b16 {%0,%1,%2,%3}, [%4];"
                 : "=r"(r[0]), "=r"(r[1]), "=r"(r[2]), "=r"(r[3]) : "r"(addr));
}
__device__ __forceinline__ void ldmatrix_x4_trans(uint32_t* r, uint32_t addr) {
    asm volatile("ldmatrix.sync.aligned.m8n8.x4.trans.shared.b16 {%0,%1,%2,%3}, [%4];"
                 : "=r"(r[0]), "=r"(r[1]), "=r"(r[2]), "=r"(r[3]) : "r"(addr));
}

extern __shared__ uint8_t dynsm[];

__global__ void __launch_bounds__(256, 2) gemm1_kernel() {
    uint8_t* sA = dynsm;                 // [3][128 rows][128 B]
    uint8_t* sB = dynsm + SB_OFF;        // [3][64 rows][256 B]

    int t = threadIdx.x;
    int lane = t & 31, warp = t >> 5;
    int wm = warp >> 1, wn = warp & 1;
    int n0 = blockIdx.x * BN;
    int m0 = blockIdx.y * BM;
    int ks = blockIdx.z;

    int am = t & 127, ah = t >> 7;
    const uint8_t* agp = (const uint8_t*)(g_xh + (size_t)(m0 + am) * ICN + ks * KCH) + ah * 64;
    uint32_t aSm[4];
#pragma unroll
    for (int j = 0; j < 4; j++) {
        int q = ah * 4 + j;
        aSm[j] = smem_u32(sA + am * 128 + ((q ^ (am & 7)) << 4));
    }
    int bkr = t >> 2, bq0 = (t & 3) * 4;
    const uint8_t* bgp = (const uint8_t*)(g_w1h + (size_t)(ks * KCH + bkr) * FC + n0) + bq0 * 16;
    uint32_t bSm[4];
#pragma unroll
    for (int j = 0; j < 4; j++) {
        int q = bq0 + j;
        bSm[j] = smem_u32(sB + bkr * 256 + ((q >> 3) << 7) + (((q & 7) ^ (bkr & 7)) << 4));
    }
    const size_t bStepG = (size_t)BK * FC * 2;

    int mRow0 = wm * 32 + (lane & 15);
    int msw = mRow0 & 7;
    int aQsel = lane >> 4;
    uint32_t aBase0 = smem_u32(sA + mRow0 * 128);
    uint32_t aBase1 = aBase0 + 16 * 128;
    int bK = lane & 15;
    uint32_t bBaseRow = smem_u32(sB + bK * 256 + wn * 128);
    int physB[4];
#pragma unroll
    for (int g = 0; g < 4; g++)
        physB[g] = ((g * 2 + (lane >> 4)) ^ (bK & 7)) << 4;

    float acc[2][8][4];
#pragma unroll
    for (int mi = 0; mi < 2; mi++)
#pragma unroll
        for (int ni = 0; ni < 8; ni++)
#pragma unroll
            for (int j = 0; j < 4; j++) acc[mi][ni][j] = 0.0f;

#pragma unroll
    for (int s = 0; s < 2; s++) {
        uint32_t ao = s * STG_A, bo = s * STG_B;
        const uint8_t* ag = agp + (size_t)s * 128;
#pragma unroll
        for (int j = 0; j < 4; j++) cp_async16(aSm[j] + ao, ag + j * 16);
        const uint8_t* bg = bgp + (size_t)s * bStepG;
#pragma unroll
        for (int j = 0; j < 4; j++) cp_async16(bSm[j] + bo, bg + j * 16);
        CP_COMMIT();
    }

    int stage = 0;
    for (int kt = 0; kt < KT2; kt++) {
        CP_WAIT(1);
        __syncthreads();

        if (kt + 2 < KT2) {
            int ws = (stage + 2 >= 3) ? stage - 1 : stage + 2;
            uint32_t ao = ws * STG_A, bo = ws * STG_B;
            const uint8_t* ag = agp + (size_t)(kt + 2) * 128;
#pragma unroll
            for (int j = 0; j < 4; j++) cp_async16(aSm[j] + ao, ag + j * 16);
            const uint8_t* bg = bgp + (size_t)(kt + 2) * bStepG;
#pragma unroll
            for (int j = 0; j < 4; j++) cp_async16(bSm[j] + bo, bg + j * 16);
            CP_COMMIT();
        }

        uint32_t ao = stage * STG_A, bo = stage * STG_B;
#pragma unroll
        for (int kk = 0; kk < BK; kk += 16) {
            uint32_t a[2][4], b[4][4];
            int qa = (kk >> 3) + aQsel;
            uint32_t aoff = ao + (uint32_t)((qa ^ msw) << 4);
            ldmatrix_x4(a[0], aBase0 + aoff);
            ldmatrix_x4(a[1], aBase1 + aoff);
            uint32_t boff = bo + (uint32_t)(kk * 256);
#pragma unroll
            for (int g = 0; g < 4; g++)
                ldmatrix_x4_trans(b[g], bBaseRow + boff + physB[g]);
#pragma unroll
            for (int mi = 0; mi < 2; mi++)
#pragma unroll
                for (int ni = 0; ni < 8; ni++) {
                    uint32_t bb0 = b[ni >> 1][(ni & 1) * 2];
                    uint32_t bb1 = b[ni >> 1][(ni & 1) * 2 + 1];
                    asm volatile(
                        "mma.sync.aligned.m16n8k16.row.col.f32.f16.f16.f32 "
                        "{%0,%1,%2,%3}, {%4,%5,%6,%7}, {%8,%9}, {%0,%1,%2,%3};"
                        : "+f"(acc[mi][ni][0]), "+f"(acc[mi][ni][1]),
                          "+f"(acc[mi][ni][2]), "+f"(acc[mi][ni][3])
                        : "r"(a[mi][0]), "r"(a[mi][1]), "r"(a[mi][2]), "r"(a[mi][3]),
                          "r"(bb0), "r"(bb1));
                }
        }
        stage = (stage + 1 >= 3) ? 0 : stage + 1;
    }

    int tig = lane & 3;
    int gid = lane >> 2;
    float* pbase = g_part[ks];
#pragma unroll
    for (int mi = 0; mi < 2; mi++) {
        int row = m0 + wm * 32 + mi * 16 + gid;
#pragma unroll
        for (int ni = 0; ni < 8; ni++) {
            int col = n0 + wn * 64 + ni * 8 + tig * 2;
            *(float2*)(pbase + (size_t)row * FC + col) =
                make_float2(acc[mi][ni][0], acc[mi][ni][1]);
            *(float2*)(pbase + (size_t)(row + 8) * FC + col) =
                make_float2(acc[mi][ni][2], acc[mi][ni][3]);
        }
    }
}

// ---------------- kernel 3b: reduce partials + bias + relu -------------------
__global__ void __launch_bounds__(256) reduce_kernel(const float* __restrict__ b1) {
    size_t i = (size_t)blockIdx.x * 256 + threadIdx.x;
    int col4 = (int)(i & 255);
    float4 p0 = ((const float4*)g_part[0])[i];
    float4 p1 = ((const float4*)g_part[1])[i];
    float4 p2 = ((const float4*)g_part[2])[i];
    float4 p3 = ((const float4*)g_part[3])[i];
    float4 bb = ((const float4*)b1)[col4];
    float4 o;
    o.x = fmaxf(p0.x + p1.x + p2.x + p3.x + bb.x, 0.0f);
    o.y = fmaxf(p0.y + p1.y + p2.y + p3.y + bb.y, 0.0f);
    o.z = fmaxf(p0.z + p1.z + p2.z + p3.z + bb.z, 0.0f);
    o.w = fmaxf(p0.w + p1.w + p2.w + p3.w + bb.w, 0.0f);
    ((float4*)g_hid)[i] = o;
}

// ---------------- kernel 4: GEMM2 + sigmoid ----------------------------------
__global__ void __launch_bounds__(256) gemm2_kernel(const float* __restrict__ b2) {
    __shared__ float sh[2][FC];
    int n0 = blockIdx.x * 2;
    int tid = threadIdx.x;

    float4* d = (float4*)&sh[0][0];
    const float4* s = (const float4*)(g_hid + (size_t)n0 * FC);
    d[tid] = s[tid];
    d[tid + 256] = s[tid + 256];
    __syncthreads();

    int warp = tid >> 5, lane = tid & 31;
    const float4* h0 = (const float4*)sh[0];
    const float4* h1 = (const float4*)sh[1];
    for (int o = warp; o < NOUT; o += 8) {
        const float4* wr = (const float4*)(g_w2t + (size_t)o * FC);
        float a0 = 0.0f, a1 = 0.0f;
#pragma unroll
        for (int i = 0; i < 8; i++) {
            float4 w = wr[i * 32 + lane];
            float4 x0 = h0[i * 32 + lane];
            float4 x1 = h1[i * 32 + lane];
            a0 += w.x * x0.x + w.y * x0.y + w.z * x0.z + w.w * x0.w;
            a1 += w.x * x1.x + w.y * x1.y + w.z * x1.z + w.w * x1.w;
        }
#pragma unroll
        for (int off = 16; off > 0; off >>= 1) {
            a0 += __shfl_xor_sync(0xffffffffu, a0, off);
            a1 += __shfl_xor_sync(0xffffffffu, a1, off);
        }
        if (lane == 0) {
            float bb = b2[o];
            g_mask[n0 * NOUT + o] = 1.0f / (1.0f + expf(-(a0 + bb)));
            g_mask[(n0 + 1) * NOUT + o] = 1.0f / (1.0f + expf(-(a1 + bb)));
        }
    }
}

// ---------------- kernel 5: out(n,c,hw) = xh(n,hw,c) * mask(n,hw) ------------
#define MPAD 261
__global__ void __launch_bounds__(256) modulate_kernel(float* __restrict__ out) {
    __shared__ float sh[25 * MPAD];
    __shared__ float msk[64];
    int n = blockIdx.x;
    int tid = threadIdx.x;
    if (tid < NOUT) msk[tid] = g_mask[n * NOUT + tid];

    const __half2* xs2 = (const __half2*)(g_xh + (size_t)n * ICN);
    float* o = out + (size_t)n * ICN;

    // chunk 0: hw 0..24
    for (int i = tid; i < 25 * 128; i += 256) {
        int hw = i >> 7, c2 = i & 127;
        float2 f = __half22float2(xs2[i]);
        sh[hw * MPAD + 2 * c2] = f.x;
        sh[hw * MPAD + 2 * c2 + 1] = f.y;
    }
    __syncthreads();
    for (int i = tid; i < 256 * 25; i += 256) {
        int c = i / 25, hw = i - c * 25;
        o[c * 49 + hw] = sh[hw * MPAD + c] * msk[hw];
    }
    __syncthreads();

    // chunk 1: hw 25..48
    for (int i = tid; i < 24 * 128; i += 256) {
        int hw = i >> 7, c2 = i & 127;
        float2 f = __half22float2(xs2[25 * 128 + i]);
        sh[hw * MPAD + 2 * c2] = f.x;
        sh[hw * MPAD + 2 * c2 + 1] = f.y;
    }
    __syncthreads();
    for (int i = tid; i < 256 * 24; i += 256) {
        int c = i / 24, hw = i - c * 24;
        o[c * 49 + 25 + hw] = sh[hw * MPAD + c] * msk[25 + hw];
    }
}

// ---------------- launcher ---------------------------------------------------
extern "C" void kernel_launch(void* const* d_in, const int* in_sizes, int n_in,
                              void* d_out, int out_size) {
    const float* features = (const float*)d_in[0];
    const float* rois     = (const float*)d_in[1];
    const float* w1       = (const float*)d_in[2];
    const float* b1       = (const float*)d_in[3];
    const float* w2       = (const float*)d_in[4];
    const float* b2       = (const float*)d_in[5];
    float* out = (float*)d_out;

    cudaFuncSetAttribute(gemm1_kernel,
                         cudaFuncAttributeMaxDynamicSharedMemorySize, 98304);

    transpose_kernel<<<dim3((HH * WW) / 32, CCH / 32, 2), 256>>>(features);
    conv_w1_kernel<<<(ICN * FC / 8) / 256, 256>>>(w1);
    conv_w2_kernel<<<(FC * NOUT + 255) / 256, 256>>>(w2);
    roi_kernel<<<dim3(NROI, 2), 256>>>(rois);
    gemm1_kernel<<<dim3(FC / BN, NROI / BM, KSPLIT), 256, 98304>>>();
    reduce_kernel<<<(NROI * FC / 4) / 256, 256>>>(b1);
    gemm2_kernel<<<NROI / 2, 256>>>(b2);
    modulate_kernel<<<NROI, 256>>>(out);
}

// round 10
// speedup vs baseline: 3.7838x; 1.0191x over previous
#include <cuda_runtime.h>
#include <cuda_fp16.h>
#include <math.h>
#include <stdint.h>

#define HH 256
#define WW 256
#define CCH 256
#define NROI 1024
#define ICN 12544          // 256 * 49
#define FC 1024
#define NOUT 49
#define KSPLIT 4
#define KCH (ICN / KSPLIT)   // 3136

// ---------------- scratch (device globals; no allocations allowed) ----------
__device__ __align__(16) __half g_feat_h[(size_t)2 * 256 * 256 * 256]; // (B,H,W,C) fp16
__device__ __align__(16) __half g_xh[(size_t)NROI * ICN];    // x fp16 (n,HW,C)
__device__ __align__(16) __half g_w1h[(size_t)ICN * FC];     // w1 fp16, K-permuted
__device__ float g_w2t[NOUT * FC];                           // w2 transposed
__device__ float g_part[KSPLIT][(size_t)NROI * FC];          // split-K partials

__device__ __forceinline__ uint32_t smem_u32(const void* p) {
    return (uint32_t)__cvta_generic_to_shared(p);
}
__device__ __forceinline__ void cp_async16(uint32_t dst, const void* src) {
    asm volatile("cp.async.cg.shared.global [%0], [%1], 16;\n" :: "r"(dst), "l"(src));
}
#define CP_COMMIT() asm volatile("cp.async.commit_group;\n")
#define CP_WAIT(n)  asm volatile("cp.async.wait_group %0;\n" :: "n"(n))

// ---------------- kernel 1: transpose (B,C,H,W) fp32 -> (B,H,W,C) fp16 -------
__global__ void __launch_bounds__(256) transpose_kernel(const float* __restrict__ f) {
    __shared__ float tile[32][33];
    int b = blockIdx.z;
    int hw0 = blockIdx.x * 32;
    int c0 = blockIdx.y * 32;
    int t = threadIdx.x;

    int ty = t >> 3, tx = t & 7;
    const float* src = f + ((size_t)b * CCH + c0 + ty) * (HH * WW) + hw0 + tx * 4;
    float4 v = *(const float4*)src;
    tile[tx * 4 + 0][ty] = v.x;
    tile[tx * 4 + 1][ty] = v.y;
    tile[tx * 4 + 2][ty] = v.z;
    tile[tx * 4 + 3][ty] = v.w;
    __syncthreads();

    int r = t >> 3, q = t & 7;
    __half2 h0 = __floats2half2_rn(tile[r][q * 4 + 0], tile[r][q * 4 + 1]);
    __half2 h1 = __floats2half2_rn(tile[r][q * 4 + 2], tile[r][q * 4 + 3]);
    uint2 o;
    o.x = *(uint32_t*)&h0;
    o.y = *(uint32_t*)&h1;
    __half* dst = g_feat_h + ((size_t)b << 24) + (size_t)(hw0 + r) * CCH + c0 + q * 4;
    *(uint2*)dst = o;
}

// ---------------- conversions ------------------------------------------------
// w1 fp16 + K-permutation: old row k = c*49+hw  ->  new row k' = hw*256+c
__global__ void __launch_bounds__(256) conv_w1_kernel(const float* __restrict__ w1) {
    size_t i = (size_t)blockIdx.x * 256 + threadIdx.x;
    int row = (int)(i >> 7);
    int col8 = (int)(i & 127);
    int c = row / 49, hw = row - c * 49;
    int nrow = hw * 256 + c;
    const float4* s = (const float4*)(w1 + (size_t)row * FC + col8 * 8);
    float4 a = s[0], bq = s[1];
    __half2 p0 = __floats2half2_rn(a.x, a.y);
    __half2 p1 = __floats2half2_rn(a.z, a.w);
    __half2 p2 = __floats2half2_rn(bq.x, bq.y);
    __half2 p3 = __floats2half2_rn(bq.z, bq.w);
    uint4 out;
    out.x = *(uint32_t*)&p0; out.y = *(uint32_t*)&p1;
    out.z = *(uint32_t*)&p2; out.w = *(uint32_t*)&p3;
    *(uint4*)(g_w1h + (size_t)nrow * FC + col8 * 8) = out;
}

__global__ void conv_w2_kernel(const float* __restrict__ w2) {
    int i = blockIdx.x * 256 + threadIdx.x;
    if (i < FC * NOUT) {
        int k = i / NOUT, o = i - k * NOUT;
        g_w2t[o * FC + k] = w2[i];
    }
}

// ---------------- kernel 2: rotated roi-align (2 blocks/roi, half2 lanes) ----
struct alignas(16) Samp { int yl, xl, yh, xh; float w11, w12, w21, w22; };

__device__ __forceinline__ void roi_bin(const __half2* __restrict__ ft2,
                                        const Samp* __restrict__ samp,
                                        int bl, float2& acc) {
    acc.x = 0.0f; acc.y = 0.0f;
#pragma unroll
    for (int s = 0; s < 4; s++) {
        const Samp* sp = &samp[bl * 4 + s];
        int4 id = *(const int4*)(&sp->yl);
        float4 w = *(const float4*)(&sp->w11);
        __half2 v11 = ft2[(id.x << 15) + (id.y << 7)];
        __half2 v12 = ft2[(id.x << 15) + (id.w << 7)];
        __half2 v21 = ft2[(id.z << 15) + (id.y << 7)];
        __half2 v22 = ft2[(id.z << 15) + (id.w << 7)];
        float2 f11 = __half22float2(v11);
        float2 f12 = __half22float2(v12);
        float2 f21 = __half22float2(v21);
        float2 f22 = __half22float2(v22);
        acc.x += w.x * f11.x + w.y * f12.x + w.z * f21.x + w.w * f22.x;
        acc.y += w.x * f11.y + w.y * f12.y + w.z * f21.y + w.w * f22.y;
    }
}

__global__ void __launch_bounds__(256, 5) roi_kernel(const float* __restrict__ rois) {
    __shared__ Samp samp[196];
    int n = blockIdx.x;
    int half = blockIdx.y;
    int tid = threadIdx.x;

    const float* r = rois + n * 6;
    int b = (int)r[0];
    float cx = r[1] * 0.125f;
    float cy = r[2] * 0.125f;
    float rw = fmaxf(r[3] * 0.125f, 1.0f);
    float rh = fmaxf(r[4] * 0.125f, 1.0f);
    float theta = r[5];
    float st, ct;
    sincosf(theta, &st, &ct);
    float bw = rw / 7.0f;
    float bh = rh / 7.0f;

    if (tid < 196) {
        int bin = tid >> 2;
        int s = tid & 3;
        int ph = bin / 7, pw = bin - ph * 7;
        int sy = s >> 1, sx = s & 1;
        float yy = -rh * 0.5f + ((float)ph + 0.25f + 0.5f * (float)sy) * bh;
        float xx = -rw * 0.5f + ((float)pw + 0.25f + 0.5f * (float)sx) * bw;
        float xs = xx * ct - yy * st + cx;
        float ys = xx * st + yy * ct + cy;
        bool valid = (ys > -1.0f) && (ys < (float)HH) && (xs > -1.0f) && (xs < (float)WW);
        float ysc = fminf(fmaxf(ys, 0.0f), (float)(HH - 1));
        float xsc = fminf(fmaxf(xs, 0.0f), (float)(WW - 1));
        int yl = (int)floorf(ysc);
        int xl = (int)floorf(xsc);
        int yh = min(yl + 1, HH - 1);
        int xh = min(xl + 1, WW - 1);
        float ly = ysc - (float)yl;
        float lx = xsc - (float)xl;
        float hy = 1.0f - ly, hx = 1.0f - lx;
        float vf = valid ? 0.25f : 0.0f;
        Samp sp;
        sp.yl = yl; sp.xl = xl; sp.yh = yh; sp.xh = xh;
        sp.w11 = hy * hx * vf; sp.w12 = hy * lx * vf;
        sp.w21 = ly * hx * vf; sp.w22 = ly * lx * vf;
        samp[tid] = sp;
    }
    __syncthreads();

    int c2 = tid & 127;        // channel-pair index: channels 2c2, 2c2+1
    int sub = tid >> 7;        // bin interleave
    const __half2* ft2 = (const __half2*)(g_feat_h + ((size_t)b << 24)) + c2;
    __half* xh = g_xh + (size_t)n * ICN + 2 * c2;

    int bstart = half * 25;
    int bend = bstart + (half ? 24 : 25);

    int bl = bstart + sub;
#pragma unroll 1
    for (; bl + 2 < bend; bl += 4) {
        float2 a0, a1;
        roi_bin(ft2, samp, bl, a0);
        roi_bin(ft2, samp, bl + 2, a1);
        *(__half2*)(xh + bl * 256) = __floats2half2_rn(a0.x, a0.y);
        *(__half2*)(xh + (bl + 2) * 256) = __floats2half2_rn(a1.x, a1.y);
    }
    if (bl < bend) {
        float2 a0;
        roi_bin(ft2, samp, bl, a0);
        *(__half2*)(xh + bl * 256) = __floats2half2_rn(a0.x, a0.y);
    }
}

// ---------------- kernel 3: GEMM1 split-K partials, fp16 HMMA ----------------
// BM=128, BN=128, BK=64, KSPLIT=4. grid (8,8,4), 256 threads (8 warps 4x2),
// warp tile 32x64. 3-stage cp.async pipeline, 96KB dynamic smem.
#define BM 128
#define BN 128
#define BK 64
#define KT2 (KCH / BK)     // 49
#define STG_A 16384
#define STG_B 16384
#define SB_OFF (3 * STG_A)

__device__ __forceinline__ void ldmatrix_x4(uint32_t* r, uint32_t addr) {
    asm volatile("ldmatrix.sync.aligned.m8n8.x4.shared.b16 {%0,%1,%2,%3}, [%4];"
                 : "=r"(r[0]), "=r"(r[1]), "=r"(r[2]), "=r"(r[3]) : "r"(addr));
}
__device__ __forceinline__ void ldmatrix_x4_trans(uint32_t* r, uint32_t addr) {
    asm volatile("ldmatrix.sync.aligned.m8n8.x4.trans.shared.b16 {%0,%1,%2,%3}, [%4];"
                 : "=r"(r[0]), "=r"(r[1]), "=r"(r[2]), "=r"(r[3]) : "r"(addr));
}

extern __shared__ uint8_t dynsm[];

__global__ void __launch_bounds__(256, 2) gemm1_kernel() {
    uint8_t* sA = dynsm;                 // [3][128 rows][128 B]
    uint8_t* sB = dynsm + SB_OFF;        // [3][64 rows][256 B]

    int t = threadIdx.x;
    int lane = t & 31, warp = t >> 5;
    int wm = warp >> 1, wn = warp & 1;
    int n0 = blockIdx.x * BN;
    int m0 = blockIdx.y * BM;
    int ks = blockIdx.z;

    int am = t & 127, ah = t >> 7;
    const uint8_t* agp = (const uint8_t*)(g_xh + (size_t)(m0 + am) * ICN + ks * KCH) + ah * 64;
    uint32_t aSm[4];
#pragma unroll
    for (int j = 0; j < 4; j++) {
        int q = ah * 4 + j;
        aSm[j] = smem_u32(sA + am * 128 + ((q ^ (am & 7)) << 4));
    }
    int bkr = t >> 2, bq0 = (t & 3) * 4;
    const uint8_t* bgp = (const uint8_t*)(g_w1h + (size_t)(ks * KCH + bkr) * FC + n0) + bq0 * 16;
    uint32_t bSm[4];
#pragma unroll
    for (int j = 0; j < 4; j++) {
        int q = bq0 + j;
        bSm[j] = smem_u32(sB + bkr * 256 + ((q >> 3) << 7) + (((q & 7) ^ (bkr & 7)) << 4));
    }
    const size_t bStepG = (size_t)BK * FC * 2;

    int mRow0 = wm * 32 + (lane & 15);
    int msw = mRow0 & 7;
    int aQsel = lane >> 4;
    uint32_t aBase0 = smem_u32(sA + mRow0 * 128);
    uint32_t aBase1 = aBase0 + 16 * 128;
    int bK = lane & 15;
    uint32_t bBaseRow = smem_u32(sB + bK * 256 + wn * 128);
    int physB[4];
#pragma unroll
    for (int g = 0; g < 4; g++)
        physB[g] = ((g * 2 + (lane >> 4)) ^ (bK & 7)) << 4;

    float acc[2][8][4];
#pragma unroll
    for (int mi = 0; mi < 2; mi++)
#pragma unroll
        for (int ni = 0; ni < 8; ni++)
#pragma unroll
            for (int j = 0; j < 4; j++) acc[mi][ni][j] = 0.0f;

#pragma unroll
    for (int s = 0; s < 2; s++) {
        uint32_t ao = s * STG_A, bo = s * STG_B;
        const uint8_t* ag = agp + (size_t)s * 128;
#pragma unroll
        for (int j = 0; j < 4; j++) cp_async16(aSm[j] + ao, ag + j * 16);
        const uint8_t* bg = bgp + (size_t)s * bStepG;
#pragma unroll
        for (int j = 0; j < 4; j++) cp_async16(bSm[j] + bo, bg + j * 16);
        CP_COMMIT();
    }

    int stage = 0;
    for (int kt = 0; kt < KT2; kt++) {
        CP_WAIT(1);
        __syncthreads();

        if (kt + 2 < KT2) {
            int ws = (stage + 2 >= 3) ? stage - 1 : stage + 2;
            uint32_t ao = ws * STG_A, bo = ws * STG_B;
            const uint8_t* ag = agp + (size_t)(kt + 2) * 128;
#pragma unroll
            for (int j = 0; j < 4; j++) cp_async16(aSm[j] + ao, ag + j * 16);
            const uint8_t* bg = bgp + (size_t)(kt + 2) * bStepG;
#pragma unroll
            for (int j = 0; j < 4; j++) cp_async16(bSm[j] + bo, bg + j * 16);
            CP_COMMIT();
        }

        uint32_t ao = stage * STG_A, bo = stage * STG_B;
#pragma unroll
        for (int kk = 0; kk < BK; kk += 16) {
            uint32_t a[2][4], b[4][4];
            int qa = (kk >> 3) + aQsel;
            uint32_t aoff = ao + (uint32_t)((qa ^ msw) << 4);
            ldmatrix_x4(a[0], aBase0 + aoff);
            ldmatrix_x4(a[1], aBase1 + aoff);
            uint32_t boff = bo + (uint32_t)(kk * 256);
#pragma unroll
            for (int g = 0; g < 4; g++)
                ldmatrix_x4_trans(b[g], bBaseRow + boff + physB[g]);
#pragma unroll
            for (int mi = 0; mi < 2; mi++)
#pragma unroll
                for (int ni = 0; ni < 8; ni++) {
                    uint32_t bb0 = b[ni >> 1][(ni & 1) * 2];
                    uint32_t bb1 = b[ni >> 1][(ni & 1) * 2 + 1];
                    asm volatile(
                        "mma.sync.aligned.m16n8k16.row.col.f32.f16.f16.f32 "
                        "{%0,%1,%2,%3}, {%4,%5,%6,%7}, {%8,%9}, {%0,%1,%2,%3};"
                        : "+f"(acc[mi][ni][0]), "+f"(acc[mi][ni][1]),
                          "+f"(acc[mi][ni][2]), "+f"(acc[mi][ni][3])
                        : "r"(a[mi][0]), "r"(a[mi][1]), "r"(a[mi][2]), "r"(a[mi][3]),
                          "r"(bb0), "r"(bb1));
                }
        }
        stage = (stage + 1 >= 3) ? 0 : stage + 1;
    }

    int tig = lane & 3;
    int gid = lane >> 2;
    float* pbase = g_part[ks];
#pragma unroll
    for (int mi = 0; mi < 2; mi++) {
        int row = m0 + wm * 32 + mi * 16 + gid;
#pragma unroll
        for (int ni = 0; ni < 8; ni++) {
            int col = n0 + wn * 64 + ni * 8 + tig * 2;
            *(float2*)(pbase + (size_t)row * FC + col) =
                make_float2(acc[mi][ni][0], acc[mi][ni][1]);
            *(float2*)(pbase + (size_t)(row + 8) * FC + col) =
                make_float2(acc[mi][ni][2], acc[mi][ni][3]);
        }
    }
}

// ---------------- kernel 4: fused tail: reduce + gemm2 + sigmoid + modulate --
// 1 block per roi, 256 threads.
#define MPAD 261
__global__ void __launch_bounds__(256) tail_kernel(const float* __restrict__ b1,
                                                   const float* __restrict__ b2,
                                                   float* __restrict__ out) {
    __shared__ float hid[FC];          // 4KB
    __shared__ float msk[64];
    __shared__ float sh[25 * MPAD];    // 26.1KB
    int n = blockIdx.x;
    int tid = threadIdx.x;

    // ---- phase 1: reduce split-K partials + bias + relu -> smem hid ----
    {
        size_t ri = (size_t)n * (FC / 4) + tid;    // float4 index into roi row
        float4 p0 = ((const float4*)g_part[0])[ri];
        float4 p1 = ((const float4*)g_part[1])[ri];
        float4 p2 = ((const float4*)g_part[2])[ri];
        float4 p3 = ((const float4*)g_part[3])[ri];
        float4 bb = ((const float4*)b1)[tid];
        float4 h;
        h.x = fmaxf(p0.x + p1.x + p2.x + p3.x + bb.x, 0.0f);
        h.y = fmaxf(p0.y + p1.y + p2.y + p3.y + bb.y, 0.0f);
        h.z = fmaxf(p0.z + p1.z + p2.z + p3.z + bb.z, 0.0f);
        h.w = fmaxf(p0.w + p1.w + p2.w + p3.w + bb.w, 0.0f);
        ((float4*)hid)[tid] = h;
    }
    __syncthreads();

    // ---- phase 2: mask = sigmoid(hid @ w2 + b2), warp per output ----
    {
        int warp = tid >> 5, lane = tid & 31;
        const float4* h4 = (const float4*)hid;
        for (int o = warp; o < NOUT; o += 8) {
            const float4* wr = (const float4*)(g_w2t + (size_t)o * FC);
            float a0 = 0.0f;
#pragma unroll
            for (int i = 0; i < 8; i++) {
                float4 w = wr[i * 32 + lane];
                float4 x0 = h4[i * 32 + lane];
                a0 += w.x * x0.x + w.y * x0.y + w.z * x0.z + w.w * x0.w;
            }
#pragma unroll
            for (int off = 16; off > 0; off >>= 1)
                a0 += __shfl_xor_sync(0xffffffffu, a0, off);
            if (lane == 0)
                msk[o] = 1.0f / (1.0f + expf(-(a0 + b2[o])));
        }
    }
    __syncthreads();

    // ---- phase 3: out(n,c,hw) = xh(n,hw,c) * msk(hw), smem transpose ----
    const __half2* xs2 = (const __half2*)(g_xh + (size_t)n * ICN);
    float* o = out + (size_t)n * ICN;

    // chunk 0: hw 0..24
    for (int i = tid; i < 25 * 128; i += 256) {
        int hw = i >> 7, c2 = i & 127;
        float2 f = __half22float2(xs2[i]);
        sh[hw * MPAD + 2 * c2] = f.x;
        sh[hw * MPAD + 2 * c2 + 1] = f.y;
    }
    __syncthreads();
    for (int i = tid; i < 256 * 25; i += 256) {
        int c = i / 25, hw = i - c * 25;
        o[c * 49 + hw] = sh[hw * MPAD + c] * msk[hw];
    }
    __syncthreads();

    // chunk 1: hw 25..48
    for (int i = tid; i < 24 * 128; i += 256) {
        int hw = i >> 7, c2 = i & 127;
        float2 f = __half22float2(xs2[25 * 128 + i]);
        sh[hw * MPAD + 2 * c2] = f.x;
        sh[hw * MPAD + 2 * c2 + 1] = f.y;
    }
    __syncthreads();
    for (int i = tid; i < 256 * 24; i += 256) {
        int c = i / 24, hw = i - c * 24;
        o[c * 49 + 25 + hw] = sh[hw * MPAD + c] * msk[25 + hw];
    }
}

// ---------------- launcher ---------------------------------------------------
extern "C" void kernel_launch(void* const* d_in, const int* in_sizes, int n_in,
                              void* d_out, int out_size) {
    const float* features = (const float*)d_in[0];
    const float* rois     = (const float*)d_in[1];
    const float* w1       = (const float*)d_in[2];
    const float* b1       = (const float*)d_in[3];
    const float* w2       = (const float*)d_in[4];
    const float* b2       = (const float*)d_in[5];
    float* out = (float*)d_out;

    cudaFuncSetAttribute(gemm1_kernel,
                         cudaFuncAttributeMaxDynamicSharedMemorySize, 98304);

    transpose_kernel<<<dim3((HH * WW) / 32, CCH / 32, 2), 256>>>(features);
    conv_w1_kernel<<<(ICN * FC / 8) / 256, 256>>>(w1);
    conv_w2_kernel<<<(FC * NOUT + 255) / 256, 256>>>(w2);
    roi_kernel<<<dim3(NROI, 2), 256>>>(rois);
    gemm1_kernel<<<dim3(FC / BN, NROI / BM, KSPLIT), 256, 98304>>>();
    tail_kernel<<<NROI, 256>>>(b1, b2, out);
}